// round 11
// baseline (speedup 1.0000x reference)
#include <cuda_runtime.h>
#include <cuda_fp16.h>
#include <cstdint>

#define N_SOTU  100000
#define N_TAXON 20000
#define NE      800000
#define NEL     200000
#define DS      256
#define DT      128
#define HID     256

#define WROW 264   // halves per weight row (256 data + 8 pad), k-major

// ---------------- scratch (device globals; no allocation) ----------------
__device__ __align__(128) __half g_aggTh[(size_t)N_TAXON*HID];
__device__ __align__(128) __half g_aggSh[(size_t)N_SOTU*HID];
__device__ __align__(128) __half g_aggSh2[(size_t)N_SOTU*HID];   // L2 sotu agg (breaks WAR)
__device__ __align__(128) __half g_h1t[(size_t)N_TAXON*HID];
__device__ __align__(128) __half g_h1s[(size_t)N_SOTU*HID];
__device__ __align__(128) __half g_us[(size_t)N_SOTU*HID];
__device__ __align__(128) __half g_ut[(size_t)N_TAXON*HID];
__device__ __align__(128) __half g_xr_s[(size_t)N_SOTU*DS];
__device__ __align__(128) __half g_xr_t[(size_t)N_TAXON*DT];
__device__ __align__(128) __half g_wt1_st[384*WROW];
__device__ __align__(128) __half g_wt1_ts[384*WROW];
__device__ __align__(128) __half g_wt2_st[512*WROW];
__device__ __align__(128) __half g_wt2_ts[512*WROW];
__device__ __align__(128) __half g_wcsT[256*WROW];
__device__ __align__(128) __half g_wctT[256*WROW];
__device__ __align__(128) float  g_bdc[256];
// CSR
__device__ int g_rowT[N_TAXON + 1];
__device__ int g_rowS[N_SOTU + 1];
__device__ int g_curT[N_TAXON];
__device__ int g_curS[N_SOTU];
__device__ int g_adjT[NE];
__device__ int g_adjS[NE];

// ---------------- prep kernels ----------------
__global__ void tohalf_dual(const float4* inA, __half2* outA, long long nA4,
                            const float4* inB, __half2* outB, long long nB4) {
    long long i = blockIdx.x * (long long)blockDim.x + threadIdx.x;
    const float4* in; __half2* out; long long idx;
    if (i < nA4) { in = inA; out = outA; idx = i; }
    else if (i - nA4 < nB4) { in = inB; out = outB; idx = i - nA4; }
    else return;
    float4 v = in[idx];
    out[idx * 2 + 0] = __floats2half2_rn(v.x, v.y);
    out[idx * 2 + 1] = __floats2half2_rn(v.z, v.w);
}

__global__ void wt_all(const float* W1a, const float* W2a, __half* Oa,
                       const float* W1b, const float* W2b, __half* Ob,
                       const float* W1c, const float* W2c, __half* Oc,
                       const float* W1d, const float* W2d, __half* Od) {
    int b = blockIdx.x, h = threadIdx.x;
    const float* W1; const float* W2; __half* O; int K1, K2, k;
    if (b < 384)        { W1 = W1a; W2 = W2a; O = Oa; K1 = 256; K2 = 128; k = b; }
    else if (b < 768)   { W1 = W1b; W2 = W2b; O = Ob; K1 = 128; K2 = 256; k = b - 384; }
    else if (b < 1280)  { W1 = W1c; W2 = W2c; O = Oc; K1 = 256; K2 = 256; k = b - 768; }
    else                { W1 = W1d; W2 = W2d; O = Od; K1 = 256; K2 = 256; k = b - 1280; }
    float v = (k < K1) ? W1[h * K1 + k] : W2[h * K2 + (k - K1)];
    O[(size_t)k * WROW + h] = __float2half_rn(v);
}

// ---------------- CSR build ----------------
__global__ void zero_dual(int* a, int na, int* b, int nb) {
    int i = blockIdx.x * blockDim.x + threadIdx.x;
    if (i < na) a[i] = 0;
    if (i < nb) b[i] = 0;
}

__global__ void hist_kernel(const int* __restrict__ src, const int* __restrict__ dst,
                            int* curS, int* curT, int E) {
    int e = blockIdx.x * blockDim.x + threadIdx.x;
    if (e < E) {
        atomicAdd(curT + dst[e], 1);
        atomicAdd(curS + src[e], 1);
    }
}

__global__ void __launch_bounds__(1024)
scan_dual(int* cntA, int* rowA, int nA, int* cntB, int* rowB, int nB) {
    int* cnt = blockIdx.x ? cntB : cntA;
    int* row = blockIdx.x ? rowB : rowA;
    int n = blockIdx.x ? nB : nA;
    __shared__ int wsum[32];
    __shared__ int carry;
    int tid = threadIdx.x, lane = tid & 31, wid = tid >> 5;
    if (tid == 0) carry = 0;
    __syncthreads();
    for (int base = 0; base < n; base += 1024) {
        int v = (base + tid < n) ? cnt[base + tid] : 0;
        int x = v;
#pragma unroll
        for (int o = 1; o < 32; o <<= 1) {
            int t = __shfl_up_sync(0xffffffffu, x, o);
            if (lane >= o) x += t;
        }
        if (lane == 31) wsum[wid] = x;
        __syncthreads();
        if (wid == 0) {
            int y = wsum[lane];
#pragma unroll
            for (int o = 1; o < 32; o <<= 1) {
                int t = __shfl_up_sync(0xffffffffu, y, o);
                if (lane >= o) y += t;
            }
            wsum[lane] = y;
        }
        __syncthreads();
        int incl = x + (wid ? wsum[wid - 1] : 0) + carry;
        if (base + tid < n) { row[base + tid] = incl - v; cnt[base + tid] = 0; }
        __syncthreads();
        if (tid == 1023) carry = incl;
        __syncthreads();
    }
    if (tid == 0) row[n] = carry;
}

__global__ void fill_kernel(const int* __restrict__ src, const int* __restrict__ dst,
                            const int* __restrict__ rowT, int* curT, int* adjT,
                            const int* __restrict__ rowS, int* curS, int* adjS, int E) {
    int e = blockIdx.x * blockDim.x + threadIdx.x;
    if (e >= E) return;
    int s = src[e], d = dst[e];
    int pT = __ldg(rowT + d) + atomicAdd(curT + d, 1);
    adjT[pT] = s;
    int pS = __ldg(rowS + s) + atomicAdd(curS + s, 1);
    adjS[pS] = d;
}

// ---------------- warp-per-node mean aggregation (unroll x4) ----------------
__global__ void agg256_kernel(const __half* __restrict__ feat,
                              const int* __restrict__ rowp,
                              const int* __restrict__ adj,
                              __half* __restrict__ out, int nNodes) {
    int gw = (blockIdx.x * blockDim.x + threadIdx.x) >> 5;
    int lane = threadIdx.x & 31;
    if (gw >= nNodes) return;
    int s = __ldg(rowp + gw), e = __ldg(rowp + gw + 1);
    float acc[8] = {0.f, 0.f, 0.f, 0.f, 0.f, 0.f, 0.f, 0.f};
    const size_t lo = (size_t)lane * 8;
    int i = s;
    for (; i + 4 <= e; i += 4) {
        int n0 = __ldg(adj + i), n1 = __ldg(adj + i + 1);
        int n2 = __ldg(adj + i + 2), n3 = __ldg(adj + i + 3);
        uint4 u0 = *(const uint4*)(feat + (size_t)n0 * 256 + lo);
        uint4 u1 = *(const uint4*)(feat + (size_t)n1 * 256 + lo);
        uint4 u2 = *(const uint4*)(feat + (size_t)n2 * 256 + lo);
        uint4 u3 = *(const uint4*)(feat + (size_t)n3 * 256 + lo);
        const __half2* h0 = (const __half2*)&u0;
        const __half2* h1 = (const __half2*)&u1;
        const __half2* h2 = (const __half2*)&u2;
        const __half2* h3 = (const __half2*)&u3;
#pragma unroll
        for (int j = 0; j < 4; j++) {
            float2 f0 = __half22float2(h0[j]);
            float2 f1 = __half22float2(h1[j]);
            float2 f2 = __half22float2(h2[j]);
            float2 f3 = __half22float2(h3[j]);
            acc[2 * j]     += (f0.x + f1.x) + (f2.x + f3.x);
            acc[2 * j + 1] += (f0.y + f1.y) + (f2.y + f3.y);
        }
    }
    for (; i < e; i++) {
        int n0 = __ldg(adj + i);
        uint4 u0 = *(const uint4*)(feat + (size_t)n0 * 256 + lo);
        const __half2* h0 = (const __half2*)&u0;
#pragma unroll
        for (int j = 0; j < 4; j++) {
            float2 f0 = __half22float2(h0[j]);
            acc[2 * j]     += f0.x;
            acc[2 * j + 1] += f0.y;
        }
    }
    float inv = 1.f / fmaxf((float)(e - s), 1.f);
    __half2 o[4];
#pragma unroll
    for (int j = 0; j < 4; j++)
        o[j] = __floats2half2_rn(acc[2 * j] * inv, acc[2 * j + 1] * inv);
    *(uint4*)(out + (size_t)gw * 256 + lo) = *(uint4*)o;
}

__global__ void agg128_kernel(const __half* __restrict__ feat,
                              const int* __restrict__ rowp,
                              const int* __restrict__ adj,
                              __half* __restrict__ out, int nNodes) {
    int gw = (blockIdx.x * blockDim.x + threadIdx.x) >> 5;
    int lane = threadIdx.x & 31;
    if (gw >= nNodes) return;
    int s = __ldg(rowp + gw), e = __ldg(rowp + gw + 1);
    float acc[4] = {0.f, 0.f, 0.f, 0.f};
    const size_t lo = (size_t)lane * 4;
    int i = s;
    for (; i + 4 <= e; i += 4) {
        int n0 = __ldg(adj + i), n1 = __ldg(adj + i + 1);
        int n2 = __ldg(adj + i + 2), n3 = __ldg(adj + i + 3);
        uint2 u0 = *(const uint2*)(feat + (size_t)n0 * 128 + lo);
        uint2 u1 = *(const uint2*)(feat + (size_t)n1 * 128 + lo);
        uint2 u2 = *(const uint2*)(feat + (size_t)n2 * 128 + lo);
        uint2 u3 = *(const uint2*)(feat + (size_t)n3 * 128 + lo);
        const __half2* h0 = (const __half2*)&u0;
        const __half2* h1 = (const __half2*)&u1;
        const __half2* h2 = (const __half2*)&u2;
        const __half2* h3 = (const __half2*)&u3;
#pragma unroll
        for (int j = 0; j < 2; j++) {
            float2 f0 = __half22float2(h0[j]);
            float2 f1 = __half22float2(h1[j]);
            float2 f2 = __half22float2(h2[j]);
            float2 f3 = __half22float2(h3[j]);
            acc[2 * j]     += (f0.x + f1.x) + (f2.x + f3.x);
            acc[2 * j + 1] += (f0.y + f1.y) + (f2.y + f3.y);
        }
    }
    for (; i < e; i++) {
        int n0 = __ldg(adj + i);
        uint2 u0 = *(const uint2*)(feat + (size_t)n0 * 128 + lo);
        const __half2* h0 = (const __half2*)&u0;
#pragma unroll
        for (int j = 0; j < 2; j++) {
            float2 f0 = __half22float2(h0[j]);
            acc[2 * j]     += f0.x;
            acc[2 * j + 1] += f0.y;
        }
    }
    float inv = 1.f / fmaxf((float)(e - s), 1.f);
    __half2 o[2];
#pragma unroll
    for (int j = 0; j < 2; j++)
        o[j] = __floats2half2_rn(acc[2 * j] * inv, acc[2 * j + 1] * inv);
    *(uint2*)(out + (size_t)gw * 128 + lo) = *(uint2*)o;
}

// ---------------- fp16 HMMA GEMM machinery (ldmatrix fragments) ----------------
#define A_ROW_B 80
#define B_ROW_B 528
#define A_STAGE_B (128*A_ROW_B)
#define B_STAGE_B (32*B_ROW_B)
#define STAGE_B   (A_STAGE_B + B_STAGE_B)
#define GEMM1_SMEM (4*STAGE_B)
#define H2_ROW_B 528
#define H2_TILE_B (128*H2_ROW_B)
#define GEMM2_SMEM (4*STAGE_B + H2_TILE_B)

__device__ __forceinline__ void mma_f16(float* d, const uint32_t* a, const uint32_t* b) {
    asm volatile(
        "mma.sync.aligned.m16n8k16.row.col.f32.f16.f16.f32 "
        "{%0,%1,%2,%3}, {%4,%5,%6,%7}, {%8,%9}, {%0,%1,%2,%3};"
        : "+f"(d[0]), "+f"(d[1]), "+f"(d[2]), "+f"(d[3])
        : "r"(a[0]), "r"(a[1]), "r"(a[2]), "r"(a[3]), "r"(b[0]), "r"(b[1]));
}
__device__ __forceinline__ void ldm_x4(uint32_t* r, uint32_t addr) {
    asm volatile("ldmatrix.sync.aligned.m8n8.x4.shared.b16 {%0,%1,%2,%3}, [%4];"
        : "=r"(r[0]), "=r"(r[1]), "=r"(r[2]), "=r"(r[3]) : "r"(addr));
}
__device__ __forceinline__ void ldm_x4t(uint32_t* r, uint32_t addr) {
    asm volatile("ldmatrix.sync.aligned.m8n8.x4.trans.shared.b16 {%0,%1,%2,%3}, [%4];"
        : "=r"(r[0]), "=r"(r[1]), "=r"(r[2]), "=r"(r[3]) : "r"(addr));
}

__device__ __forceinline__ void issue_ab(uint32_t sbase, int c, int k0, int K1,
                                         const __half* A1, const __half* A2, int K2,
                                         const __half* WTk, int bm, int Nrows, int tid) {
    int slot = c & 3;
    uint32_t aoff = sbase + slot * STAGE_B;
    uint32_t boff = aoff + A_STAGE_B;
    bool inA1 = (k0 < K1);
#pragma unroll
    for (int i = 0; i < 2; i++) {
        int idx = tid + i * 256;
        int row = idx >> 2, seg8 = (idx & 3) * 8;
        int grow = bm + row;
        bool ok = grow < Nrows;
        int gr = ok ? grow : 0;
        const __half* src = inA1 ? A1 + (size_t)gr * K1 + k0 + seg8
                                 : A2 + (size_t)gr * K2 + (k0 - K1) + seg8;
        uint32_t dst = aoff + (uint32_t)(row * A_ROW_B + seg8 * 2);
        int sz = ok ? 16 : 0;
        asm volatile("cp.async.cg.shared.global [%0], [%1], 16, %2;"
                     :: "r"(dst), "l"(src), "r"(sz));
    }
#pragma unroll
    for (int i = 0; i < 4; i++) {
        int idx = tid + i * 256;
        int kr = idx >> 5, seg = idx & 31;
        const __half* src = WTk + (size_t)(k0 + kr) * WROW + seg * 8;
        uint32_t dst = boff + (uint32_t)(kr * B_ROW_B + seg * 16);
        asm volatile("cp.async.cg.shared.global [%0], [%1], 16;"
                     :: "r"(dst), "l"(src));
    }
    asm volatile("cp.async.commit_group;");
}

__device__ __forceinline__ void issue_b(uint32_t sbase, int c, const __half* P, int tid) {
    int slot = c & 3;
    uint32_t boff = sbase + slot * STAGE_B + A_STAGE_B;
    int k0 = c << 5;
#pragma unroll
    for (int i = 0; i < 4; i++) {
        int idx = tid + i * 256;
        int kr = idx >> 5, seg = idx & 31;
        const __half* src = P + (size_t)(k0 + kr) * WROW + seg * 8;
        uint32_t dst = boff + (uint32_t)(kr * B_ROW_B + seg * 16);
        asm volatile("cp.async.cg.shared.global [%0], [%1], 16;"
                     :: "r"(dst), "l"(src));
    }
    asm volatile("cp.async.commit_group;");
}

__device__ __forceinline__ void mma_chunk(uint32_t aBase, uint32_t bBase, float acc[4][8][4]) {
#pragma unroll
    for (int s = 0; s < 2; s++) {
        uint32_t af[4][4], bf[4][4];
#pragma unroll
        for (int mt = 0; mt < 4; mt++)
            ldm_x4(af[mt], aBase + mt * (16 * A_ROW_B) + s * 32);
#pragma unroll
        for (int p = 0; p < 4; p++)
            ldm_x4t(bf[p], bBase + s * (16 * B_ROW_B) + p * 32);
#pragma unroll
        for (int mt = 0; mt < 4; mt++)
#pragma unroll
            for (int p = 0; p < 4; p++) {
                mma_f16(acc[mt][2 * p],     af[mt], &bf[p][0]);
                mma_f16(acc[mt][2 * p + 1], af[mt], &bf[p][2]);
            }
    }
}

// ---------------- layer-1 GEMM: relu epilogue ----------------
__global__ void __launch_bounds__(256)
gemm_sage(const __half* A1, int K1, const __half* A2, int K2,
          const __half* W, const float* bias, __half* C, int Nrows) {
    extern __shared__ char sm[];
    const int tid = threadIdx.x;
    const int wid = tid >> 5, lane = tid & 31;
    const int warpM = wid >> 2, warpN = wid & 3;
    const int lrow = lane >> 2, lcol = lane & 3;
    const int bm = blockIdx.x * 128;
    const int nch = (K1 + K2) >> 5;

    uint32_t sbase = (uint32_t)__cvta_generic_to_shared(sm);
    const uint32_t aLane = (uint32_t)((warpM * 64 + (lane & 15)) * A_ROW_B + ((lane & 16) ? 16 : 0));
    const uint32_t bLane = (uint32_t)((lane & 15) * B_ROW_B + (warpN * 64 + ((lane & 16) ? 8 : 0)) * 2);

    float2 bv[8];
#pragma unroll
    for (int nt = 0; nt < 8; nt++) {
        int col = warpN * 64 + nt * 8 + 2 * lcol;
        bv[nt].x = __ldg(bias + col); bv[nt].y = __ldg(bias + col + 1);
    }

    float acc[4][8][4];
#pragma unroll
    for (int i = 0; i < 4; i++)
#pragma unroll
        for (int j = 0; j < 8; j++)
#pragma unroll
            for (int q = 0; q < 4; q++) acc[i][j][q] = 0.f;

    issue_ab(sbase, 0, 0, K1, A1, A2, K2, W, bm, Nrows, tid);
    issue_ab(sbase, 1, 32, K1, A1, A2, K2, W, bm, Nrows, tid);
    issue_ab(sbase, 2, 64, K1, A1, A2, K2, W, bm, Nrows, tid);

    for (int c = 0; c < nch; c++) {
        asm volatile("cp.async.wait_group 2;");
        __syncthreads();
        if (c + 3 < nch) issue_ab(sbase, c + 3, (c + 3) << 5, K1, A1, A2, K2, W, bm, Nrows, tid);
        else asm volatile("cp.async.commit_group;");
        int slot = c & 3;
        mma_chunk(sbase + slot * STAGE_B + aLane,
                  sbase + slot * STAGE_B + A_STAGE_B + bLane, acc);
    }

#pragma unroll
    for (int mt = 0; mt < 4; mt++) {
        const int r0 = bm + warpM * 64 + mt * 16 + lrow;
#pragma unroll
        for (int half = 0; half < 2; half++) {
            const int row = r0 + half * 8;
            if (row >= Nrows) continue;
#pragma unroll
            for (int nt = 0; nt < 8; nt++) {
                const int col = warpN * 64 + nt * 8 + 2 * lcol;
                float vx = fmaxf(acc[mt][nt][half * 2 + 0] + bv[nt].x, 0.f);
                float vy = fmaxf(acc[mt][nt][half * 2 + 1] + bv[nt].y, 0.f);
                *(__half2*)(C + (size_t)row * 256 + col) = __floats2half2_rn(vx, vy);
            }
        }
    }
}

// ---------------- layer-2 GEMM + fused projection ----------------
__global__ void __launch_bounds__(256)
gemm_l2p(const __half* A1, const __half* A2, const __half* W, const float* bias,
         const __half* P, __half* U, int Nrows) {
    extern __shared__ char sm[];
    const int tid = threadIdx.x;
    const int wid = tid >> 5, lane = tid & 31;
    const int warpM = wid >> 2, warpN = wid & 3;
    const int lrow = lane >> 2, lcol = lane & 3;
    const int bm = blockIdx.x * 128;
    const int K1 = HID;
    const int nch = 16;

    uint32_t sbase = (uint32_t)__cvta_generic_to_shared(sm);
    uint32_t* H2 = (uint32_t*)(sm + 4 * STAGE_B);
    const uint32_t h2base = sbase + 4 * STAGE_B;
    const uint32_t aLane = (uint32_t)((warpM * 64 + (lane & 15)) * A_ROW_B + ((lane & 16) ? 16 : 0));
    const uint32_t bLane = (uint32_t)((lane & 15) * B_ROW_B + (warpN * 64 + ((lane & 16) ? 8 : 0)) * 2);
    const uint32_t h2Lane = h2base + (uint32_t)((warpM * 64 + (lane & 15)) * H2_ROW_B + ((lane & 16) ? 16 : 0));

    float2 bv[8];
#pragma unroll
    for (int nt = 0; nt < 8; nt++) {
        int col = warpN * 64 + nt * 8 + 2 * lcol;
        bv[nt].x = __ldg(bias + col); bv[nt].y = __ldg(bias + col + 1);
    }

    float acc[4][8][4];
#pragma unroll
    for (int i = 0; i < 4; i++)
#pragma unroll
        for (int j = 0; j < 8; j++)
#pragma unroll
            for (int q = 0; q < 4; q++) acc[i][j][q] = 0.f;

    issue_ab(sbase, 0, 0, K1, A1, A2, HID, W, bm, Nrows, tid);
    issue_ab(sbase, 1, 32, K1, A1, A2, HID, W, bm, Nrows, tid);
    issue_ab(sbase, 2, 64, K1, A1, A2, HID, W, bm, Nrows, tid);

    for (int c = 0; c < nch; c++) {
        asm volatile("cp.async.wait_group 2;");
        __syncthreads();
        if (c + 3 < nch) issue_ab(sbase, c + 3, (c + 3) << 5, K1, A1, A2, HID, W, bm, Nrows, tid);
        else asm volatile("cp.async.commit_group;");
        int slot = c & 3;
        mma_chunk(sbase + slot * STAGE_B + aLane,
                  sbase + slot * STAGE_B + A_STAGE_B + bLane, acc);
    }

    // store h2 tile (bias+relu, half) into smem; re-zero acc
#pragma unroll
    for (int mt = 0; mt < 4; mt++) {
#pragma unroll
        for (int half = 0; half < 2; half++) {
            const int row = warpM * 64 + mt * 16 + lrow + half * 8;
#pragma unroll
            for (int nt = 0; nt < 8; nt++) {
                const int col2 = warpN * 32 + nt * 4 + lcol;
                float vx = fmaxf(acc[mt][nt][half * 2 + 0] + bv[nt].x, 0.f);
                float vy = fmaxf(acc[mt][nt][half * 2 + 1] + bv[nt].y, 0.f);
                __half2 hv = __floats2half2_rn(vx, vy);
                H2[row * (H2_ROW_B / 4) + col2] = *(uint32_t*)&hv;
            }
        }
    }
#pragma unroll
    for (int i = 0; i < 4; i++)
#pragma unroll
        for (int j = 0; j < 8; j++)
#pragma unroll
            for (int q = 0; q < 4; q++) acc[i][j][q] = 0.f;
    __syncthreads();

    // projection loop: u = h2 @ P
    issue_b(sbase, 0, P, tid);
    issue_b(sbase, 1, P, tid);
    issue_b(sbase, 2, P, tid);

    for (int c = 0; c < 8; c++) {
        asm volatile("cp.async.wait_group 2;");
        __syncthreads();
        if (c + 3 < 8) issue_b(sbase, c + 3, P, tid);
        else asm volatile("cp.async.commit_group;");
        int slot = c & 3;
        uint32_t bB = sbase + slot * STAGE_B + A_STAGE_B + bLane;
#pragma unroll
        for (int s = 0; s < 2; s++) {
            uint32_t af[4][4], bf[4][4];
#pragma unroll
            for (int mt = 0; mt < 4; mt++)
                ldm_x4(af[mt], h2Lane + mt * (16 * H2_ROW_B) + c * 64 + s * 32);
#pragma unroll
            for (int p = 0; p < 4; p++)
                ldm_x4t(bf[p], bB + s * (16 * B_ROW_B) + p * 32);
#pragma unroll
            for (int mt = 0; mt < 4; mt++)
#pragma unroll
                for (int p = 0; p < 4; p++) {
                    mma_f16(acc[mt][2 * p],     af[mt], &bf[p][0]);
                    mma_f16(acc[mt][2 * p + 1], af[mt], &bf[p][2]);
                }
        }
    }

#pragma unroll
    for (int mt = 0; mt < 4; mt++) {
        const int r0 = bm + warpM * 64 + mt * 16 + lrow;
#pragma unroll
        for (int half = 0; half < 2; half++) {
            const int row = r0 + half * 8;
            if (row >= Nrows) continue;
#pragma unroll
            for (int nt = 0; nt < 8; nt++) {
                const int col = warpN * 64 + nt * 8 + 2 * lcol;
                *(__half2*)(U + (size_t)row * 256 + col) =
                    __floats2half2_rn(acc[mt][nt][half * 2 + 0], acc[mt][nt][half * 2 + 1]);
            }
        }
    }
}

// ---------------- weight composition (k-major half output) ----------------
__global__ void compose_kernel(const float* __restrict__ Wd1,
                               const float* __restrict__ Wlin_s,
                               const float* __restrict__ Wlin_t,
                               const float* __restrict__ blin_s,
                               const float* __restrict__ blin_t,
                               const float* __restrict__ bd1,
                               __half* WcsT, __half* WctT, float* bdc) {
    int i = blockIdx.x;
    int m = threadIdx.x;
    float ss = 0.f, st = 0.f;
    for (int k = 0; k < HID; k++) {
        float wl = Wd1[i * 2 * HID + k];
        float wr = Wd1[i * 2 * HID + HID + k];
        ss += wl * Wlin_s[k * HID + m];
        st += wr * Wlin_t[k * HID + m];
    }
    WcsT[(size_t)m * WROW + i] = __float2half_rn(ss);
    WctT[(size_t)m * WROW + i] = __float2half_rn(st);
    if (m == 0) {
        float b = bd1[i];
        for (int k = 0; k < HID; k++) {
            b += Wd1[i * 2 * HID + k] * blin_s[k];
            b += Wd1[i * 2 * HID + HID + k] * blin_t[k];
        }
        bdc[i] = b;
    }
}

// ---------------- decoder ----------------
__global__ void decode_kernel(const __half* __restrict__ us, const __half* __restrict__ ut,
                              const int* __restrict__ ls, const int* __restrict__ ld,
                              const float4* __restrict__ bdc, const float4* __restrict__ wd2,
                              const float* __restrict__ bd2,
                              float* __restrict__ out, int EL) {
    int g = blockIdx.x * blockDim.x + threadIdx.x;
    int w = g >> 5, lane = g & 31;
    if (w >= EL) return;
    const uint4* a = (const uint4*)(us + (size_t)__ldg(ls + w) * HID);
    const uint4* b = (const uint4*)(ut + (size_t)__ldg(ld + w) * HID);
    uint4 ua = a[lane], ub = b[lane];
    float4 c0 = bdc[lane * 2], c1 = bdc[lane * 2 + 1];
    float4 w0 = wd2[lane * 2], w1 = wd2[lane * 2 + 1];
    float2 a0 = __half22float2(*(__half2*)&ua.x), b0 = __half22float2(*(__half2*)&ub.x);
    float2 a1 = __half22float2(*(__half2*)&ua.y), b1 = __half22float2(*(__half2*)&ub.y);
    float2 a2 = __half22float2(*(__half2*)&ua.z), b2 = __half22float2(*(__half2*)&ub.z);
    float2 a3 = __half22float2(*(__half2*)&ua.w), b3 = __half22float2(*(__half2*)&ub.w);
    float sum =
        fmaxf(a0.x + b0.x + c0.x, 0.f) * w0.x + fmaxf(a0.y + b0.y + c0.y, 0.f) * w0.y +
        fmaxf(a1.x + b1.x + c0.z, 0.f) * w0.z + fmaxf(a1.y + b1.y + c0.w, 0.f) * w0.w +
        fmaxf(a2.x + b2.x + c1.x, 0.f) * w1.x + fmaxf(a2.y + b2.y + c1.y, 0.f) * w1.y +
        fmaxf(a3.x + b3.x + c1.z, 0.f) * w1.z + fmaxf(a3.y + b3.y + c1.w, 0.f) * w1.w;
#pragma unroll
    for (int o = 16; o; o >>= 1) sum += __shfl_xor_sync(0xffffffffu, sum, o);
    if (lane == 0) out[w] = sum + bd2[0];
}

// ---------------- launcher ----------------
extern "C" void kernel_launch(void* const* d_in, const int* in_sizes, int n_in,
                              void* d_out, int out_size) {
    const float* x_sotu  = (const float*)d_in[0];
    const float* x_taxon = (const float*)d_in[1];
    const int*   esrc    = (const int*)d_in[2];
    const int*   edst    = (const int*)d_in[3];
    const int*   lsrc    = (const int*)d_in[4];
    const int*   ldst    = (const int*)d_in[5];
    const float* Wl1_st  = (const float*)d_in[6];
    const float* bl1_st  = (const float*)d_in[7];
    const float* Wr1_st  = (const float*)d_in[8];
    const float* Wl1_ts  = (const float*)d_in[9];
    const float* bl1_ts  = (const float*)d_in[10];
    const float* Wr1_ts  = (const float*)d_in[11];
    const float* Wl2_st  = (const float*)d_in[12];
    const float* bl2_st  = (const float*)d_in[13];
    const float* Wr2_st  = (const float*)d_in[14];
    const float* Wl2_ts  = (const float*)d_in[15];
    const float* bl2_ts  = (const float*)d_in[16];
    const float* Wr2_ts  = (const float*)d_in[17];
    const float* Wlin_s  = (const float*)d_in[18];
    const float* blin_s  = (const float*)d_in[19];
    const float* Wlin_t  = (const float*)d_in[20];
    const float* blin_t  = (const float*)d_in[21];
    const float* Wd1     = (const float*)d_in[22];
    const float* bd1     = (const float*)d_in[23];
    const float* Wd2     = (const float*)d_in[24];
    const float* bd2     = (const float*)d_in[25];
    float* out = (float*)d_out;

    float *bdc;
    __half *aggTh, *aggSh, *aggSh2, *h1t, *h1s, *us, *ut;
    __half *xrs, *xrt, *wt1st, *wt1ts, *wt2st, *wt2ts, *wcsT, *wctT;
    int *rowT, *rowS, *curT, *curS, *adjT, *adjS;
    cudaGetSymbolAddress((void**)&aggTh, g_aggTh);
    cudaGetSymbolAddress((void**)&aggSh, g_aggSh);
    cudaGetSymbolAddress((void**)&aggSh2, g_aggSh2);
    cudaGetSymbolAddress((void**)&h1t, g_h1t);
    cudaGetSymbolAddress((void**)&h1s, g_h1s);
    cudaGetSymbolAddress((void**)&us,  g_us);
    cudaGetSymbolAddress((void**)&ut,  g_ut);
    cudaGetSymbolAddress((void**)&xrs, g_xr_s);
    cudaGetSymbolAddress((void**)&xrt, g_xr_t);
    cudaGetSymbolAddress((void**)&wt1st, g_wt1_st);
    cudaGetSymbolAddress((void**)&wt1ts, g_wt1_ts);
    cudaGetSymbolAddress((void**)&wt2st, g_wt2_st);
    cudaGetSymbolAddress((void**)&wt2ts, g_wt2_ts);
    cudaGetSymbolAddress((void**)&wcsT, g_wcsT);
    cudaGetSymbolAddress((void**)&wctT, g_wctT);
    cudaGetSymbolAddress((void**)&bdc, g_bdc);
    cudaGetSymbolAddress((void**)&rowT, g_rowT);
    cudaGetSymbolAddress((void**)&rowS, g_rowS);
    cudaGetSymbolAddress((void**)&curT, g_curT);
    cudaGetSymbolAddress((void**)&curS, g_curS);
    cudaGetSymbolAddress((void**)&adjT, g_adjT);
    cudaGetSymbolAddress((void**)&adjS, g_adjS);

    // one-time resources (created on the uncaptured correctness call)
    static cudaStream_t s2 = nullptr, s3 = nullptr;
    static cudaEvent_t ev[12];
    static int inited = 0;
    if (!inited) {
        cudaFuncSetAttribute(gemm_sage, cudaFuncAttributeMaxDynamicSharedMemorySize, GEMM1_SMEM);
        cudaFuncSetAttribute(gemm_l2p, cudaFuncAttributeMaxDynamicSharedMemorySize, GEMM2_SMEM);
        cudaStreamCreateWithFlags(&s2, cudaStreamNonBlocking);
        cudaStreamCreateWithFlags(&s3, cudaStreamNonBlocking);
        for (int i = 0; i < 12; i++) cudaEventCreateWithFlags(&ev[i], cudaEventDisableTiming);
        inited = 1;
    }
    cudaStream_t s0 = 0;

    const int gT = (N_TAXON + 127) / 128;   // 157
    const int gS = (N_SOTU + 127) / 128;    // 782
    const unsigned wT = (N_TAXON * 32 + 255) / 256;
    const unsigned wS = (N_SOTU * 32 + 255) / 256;

    // ---- fork from origin ----
    cudaEventRecord(ev[0], s0);
    cudaStreamWaitEvent(s2, ev[0], 0);
    cudaStreamWaitEvent(s3, ev[0], 0);

    // prep on s0
    long long nxs4 = (long long)N_SOTU * DS / 4, nxt4 = (long long)N_TAXON * DT / 4;
    tohalf_dual<<<(unsigned)((nxs4 + nxt4 + 255) / 256), 256, 0, s0>>>(
        (const float4*)x_sotu, (__half2*)xrs, nxs4,
        (const float4*)x_taxon, (__half2*)xrt, nxt4);
    wt_all<<<1792, 256, 0, s0>>>(Wl1_st, Wr1_st, wt1st,
                                 Wl1_ts, Wr1_ts, wt1ts,
                                 Wl2_st, Wr2_st, wt2st,
                                 Wl2_ts, Wr2_ts, wt2ts);
    compose_kernel<<<HID, HID, 0, s0>>>(Wd1, Wlin_s, Wlin_t, blin_s, blin_t, bd1, wcsT, wctT, bdc);
    cudaEventRecord(ev[1], s0);          // evPREP

    // CSR on s2
    zero_dual<<<(N_SOTU + 255) / 256, 256, 0, s2>>>(curT, N_TAXON, curS, N_SOTU);
    hist_kernel<<<(NE + 255) / 256, 256, 0, s2>>>(esrc, edst, curS, curT, NE);
    scan_dual<<<2, 1024, 0, s2>>>(curT, rowT, N_TAXON, curS, rowS, N_SOTU);
    fill_kernel<<<(NE + 255) / 256, 256, 0, s2>>>(esrc, edst, rowT, curT, adjT, rowS, curS, adjS, NE);
    cudaEventRecord(ev[2], s2);          // evCSR

    // ---- layer 1 ----
    // taxon chain on s0 (needs CSR; prep already on s0)
    cudaStreamWaitEvent(s0, ev[2], 0);
    agg256_kernel<<<wT, 256, 0, s0>>>(xrs, rowT, adjT, aggTh, N_TAXON);
    gemm_sage<<<(unsigned)gT, 256, GEMM1_SMEM, s0>>>(aggTh, DS, xrt, DT, wt1st, bl1_st, h1t, N_TAXON);
    cudaEventRecord(ev[3], s0);          // evH1T

    // sotu chain on s2 -> s3 (needs prep for xrt/xrs)
    cudaStreamWaitEvent(s2, ev[1], 0);
    agg128_kernel<<<wS, 256, 0, s2>>>(xrt, rowS, adjS, aggSh, N_SOTU);
    cudaEventRecord(ev[4], s2);          // evAGG_S_L1

    cudaStreamWaitEvent(s3, ev[4], 0);
    gemm_sage<<<(unsigned)gS, 256, GEMM1_SMEM, s3>>>(aggSh, DT, xrs, DS, wt1ts, bl1_ts, h1s, N_SOTU);
    cudaEventRecord(ev[6], s3);          // evH1S

    // ---- layer 2 ----
    // L2 sotu agg on s2: reads ONLY h1t, writes aggSh2 (no WAR on aggSh) -> starts early
    cudaStreamWaitEvent(s2, ev[3], 0);
    agg256_kernel<<<wS, 256, 0, s2>>>(h1t, rowS, adjS, aggSh2, N_SOTU);
    cudaEventRecord(ev[7], s2);          // evAGG_S_L2

    // taxon L2 chain on s0 (reads h1s)
    cudaStreamWaitEvent(s0, ev[6], 0);
    agg256_kernel<<<wT, 256, 0, s0>>>(h1s, rowT, adjT, aggTh, N_TAXON);
    gemm_l2p<<<(unsigned)gT, 256, GEMM2_SMEM, s0>>>(aggTh, h1t, wt2st, bl2_st, wctT, ut, N_TAXON);

    // sotu L2 gemm on s3 (needs aggSh2 + h1s)
    cudaStreamWaitEvent(s3, ev[7], 0);
    gemm_l2p<<<(unsigned)gS, 256, GEMM2_SMEM, s3>>>(aggSh2, h1s, wt2ts, bl2_ts, wcsT, us, N_SOTU);
    cudaEventRecord(ev[9], s3);          // evU

    // ---- join + decode on s0 ----
    cudaStreamWaitEvent(s0, ev[9], 0);
    decode_kernel<<<(NEL * 32 + 255) / 256, 256, 0, s0>>>(
        us, ut, lsrc, ldst,
        (const float4*)bdc, (const float4*)Wd2, bd2, out, NEL);
}

// round 12
// speedup vs baseline: 1.0042x; 1.0042x over previous
#include <cuda_runtime.h>
#include <cuda_fp16.h>
#include <cstdint>

#define N_SOTU  100000
#define N_TAXON 20000
#define NE      800000
#define NEL     200000
#define DS      256
#define DT      128
#define HID     256

#define WROW 264   // halves per weight row (256 data + 8 pad), k-major

// ---------------- scratch (device globals; no allocation) ----------------
__device__ __align__(128) __half g_aggTh[(size_t)N_TAXON*HID];
__device__ __align__(128) __half g_aggSh[(size_t)N_SOTU*HID];
__device__ __align__(128) __half g_h1t[(size_t)N_TAXON*HID];
__device__ __align__(128) __half g_h1s[(size_t)N_SOTU*HID];
__device__ __align__(128) __half g_us[(size_t)N_SOTU*HID];
__device__ __align__(128) __half g_ut[(size_t)N_TAXON*HID];
__device__ __align__(128) __half g_xr_s[(size_t)N_SOTU*DS];
__device__ __align__(128) __half g_xr_t[(size_t)N_TAXON*DT];
__device__ __align__(128) __half g_wt1_st[384*WROW];
__device__ __align__(128) __half g_wt1_ts[384*WROW];
__device__ __align__(128) __half g_wt2_st[512*WROW];
__device__ __align__(128) __half g_wt2_ts[512*WROW];
__device__ __align__(128) __half g_wcsT[256*WROW];
__device__ __align__(128) __half g_wctT[256*WROW];
__device__ __align__(128) float  g_bdc[256];
// CSR
__device__ int g_rowT[N_TAXON + 1];
__device__ int g_rowS[N_SOTU + 1];
__device__ int g_curT[N_TAXON];
__device__ int g_curS[N_SOTU];
__device__ int g_adjT[NE];
__device__ int g_adjS[NE];

// ---------------- prep kernels ----------------
__global__ void tohalf_dual(const float4* inA, __half2* outA, long long nA4,
                            const float4* inB, __half2* outB, long long nB4) {
    long long i = blockIdx.x * (long long)blockDim.x + threadIdx.x;
    const float4* in; __half2* out; long long idx;
    if (i < nA4) { in = inA; out = outA; idx = i; }
    else if (i - nA4 < nB4) { in = inB; out = outB; idx = i - nA4; }
    else return;
    float4 v = in[idx];
    out[idx * 2 + 0] = __floats2half2_rn(v.x, v.y);
    out[idx * 2 + 1] = __floats2half2_rn(v.z, v.w);
}

__global__ void wt_all(const float* W1a, const float* W2a, __half* Oa,
                       const float* W1b, const float* W2b, __half* Ob,
                       const float* W1c, const float* W2c, __half* Oc,
                       const float* W1d, const float* W2d, __half* Od) {
    int b = blockIdx.x, h = threadIdx.x;
    const float* W1; const float* W2; __half* O; int K1, K2, k;
    if (b < 384)        { W1 = W1a; W2 = W2a; O = Oa; K1 = 256; K2 = 128; k = b; }
    else if (b < 768)   { W1 = W1b; W2 = W2b; O = Ob; K1 = 128; K2 = 256; k = b - 384; }
    else if (b < 1280)  { W1 = W1c; W2 = W2c; O = Oc; K1 = 256; K2 = 256; k = b - 768; }
    else                { W1 = W1d; W2 = W2d; O = Od; K1 = 256; K2 = 256; k = b - 1280; }
    float v = (k < K1) ? W1[h * K1 + k] : W2[h * K2 + (k - K1)];
    O[(size_t)k * WROW + h] = __float2half_rn(v);
}

// ---------------- CSR build ----------------
__global__ void zero_dual(int* a, int na, int* b, int nb) {
    int i = blockIdx.x * blockDim.x + threadIdx.x;
    if (i < na) a[i] = 0;
    if (i < nb) b[i] = 0;
}

__global__ void hist_kernel(const int* __restrict__ src, const int* __restrict__ dst,
                            int* curS, int* curT, int E) {
    int e = blockIdx.x * blockDim.x + threadIdx.x;
    if (e < E) {
        atomicAdd(curT + dst[e], 1);
        atomicAdd(curS + src[e], 1);
    }
}

__global__ void __launch_bounds__(1024)
scan_dual(int* cntA, int* rowA, int nA, int* cntB, int* rowB, int nB) {
    int* cnt = blockIdx.x ? cntB : cntA;
    int* row = blockIdx.x ? rowB : rowA;
    int n = blockIdx.x ? nB : nA;
    __shared__ int wsum[32];
    __shared__ int carry;
    int tid = threadIdx.x, lane = tid & 31, wid = tid >> 5;
    if (tid == 0) carry = 0;
    __syncthreads();
    for (int base = 0; base < n; base += 1024) {
        int v = (base + tid < n) ? cnt[base + tid] : 0;
        int x = v;
#pragma unroll
        for (int o = 1; o < 32; o <<= 1) {
            int t = __shfl_up_sync(0xffffffffu, x, o);
            if (lane >= o) x += t;
        }
        if (lane == 31) wsum[wid] = x;
        __syncthreads();
        if (wid == 0) {
            int y = wsum[lane];
#pragma unroll
            for (int o = 1; o < 32; o <<= 1) {
                int t = __shfl_up_sync(0xffffffffu, y, o);
                if (lane >= o) y += t;
            }
            wsum[lane] = y;
        }
        __syncthreads();
        int incl = x + (wid ? wsum[wid - 1] : 0) + carry;
        if (base + tid < n) { row[base + tid] = incl - v; cnt[base + tid] = 0; }
        __syncthreads();
        if (tid == 1023) carry = incl;
        __syncthreads();
    }
    if (tid == 0) row[n] = carry;
}

__global__ void fill_kernel(const int* __restrict__ src, const int* __restrict__ dst,
                            const int* __restrict__ rowT, int* curT, int* adjT,
                            const int* __restrict__ rowS, int* curS, int* adjS, int E) {
    int e = blockIdx.x * blockDim.x + threadIdx.x;
    if (e >= E) return;
    int s = src[e], d = dst[e];
    int pT = __ldg(rowT + d) + atomicAdd(curT + d, 1);
    adjT[pT] = s;
    int pS = __ldg(rowS + s) + atomicAdd(curS + s, 1);
    adjS[pS] = d;
}

// ---------------- warp-per-node mean aggregation (unroll x4) ----------------
__global__ void agg256_kernel(const __half* __restrict__ feat,
                              const int* __restrict__ rowp,
                              const int* __restrict__ adj,
                              __half* __restrict__ out, int nNodes) {
    int gw = (blockIdx.x * blockDim.x + threadIdx.x) >> 5;
    int lane = threadIdx.x & 31;
    if (gw >= nNodes) return;
    int s = __ldg(rowp + gw), e = __ldg(rowp + gw + 1);
    float acc[8] = {0.f, 0.f, 0.f, 0.f, 0.f, 0.f, 0.f, 0.f};
    const size_t lo = (size_t)lane * 8;
    int i = s;
    for (; i + 4 <= e; i += 4) {
        int n0 = __ldg(adj + i), n1 = __ldg(adj + i + 1);
        int n2 = __ldg(adj + i + 2), n3 = __ldg(adj + i + 3);
        uint4 u0 = *(const uint4*)(feat + (size_t)n0 * 256 + lo);
        uint4 u1 = *(const uint4*)(feat + (size_t)n1 * 256 + lo);
        uint4 u2 = *(const uint4*)(feat + (size_t)n2 * 256 + lo);
        uint4 u3 = *(const uint4*)(feat + (size_t)n3 * 256 + lo);
        const __half2* h0 = (const __half2*)&u0;
        const __half2* h1 = (const __half2*)&u1;
        const __half2* h2 = (const __half2*)&u2;
        const __half2* h3 = (const __half2*)&u3;
#pragma unroll
        for (int j = 0; j < 4; j++) {
            float2 f0 = __half22float2(h0[j]);
            float2 f1 = __half22float2(h1[j]);
            float2 f2 = __half22float2(h2[j]);
            float2 f3 = __half22float2(h3[j]);
            acc[2 * j]     += (f0.x + f1.x) + (f2.x + f3.x);
            acc[2 * j + 1] += (f0.y + f1.y) + (f2.y + f3.y);
        }
    }
    for (; i < e; i++) {
        int n0 = __ldg(adj + i);
        uint4 u0 = *(const uint4*)(feat + (size_t)n0 * 256 + lo);
        const __half2* h0 = (const __half2*)&u0;
#pragma unroll
        for (int j = 0; j < 4; j++) {
            float2 f0 = __half22float2(h0[j]);
            acc[2 * j]     += f0.x;
            acc[2 * j + 1] += f0.y;
        }
    }
    float inv = 1.f / fmaxf((float)(e - s), 1.f);
    __half2 o[4];
#pragma unroll
    for (int j = 0; j < 4; j++)
        o[j] = __floats2half2_rn(acc[2 * j] * inv, acc[2 * j + 1] * inv);
    *(uint4*)(out + (size_t)gw * 256 + lo) = *(uint4*)o;
}

__global__ void agg128_kernel(const __half* __restrict__ feat,
                              const int* __restrict__ rowp,
                              const int* __restrict__ adj,
                              __half* __restrict__ out, int nNodes) {
    int gw = (blockIdx.x * blockDim.x + threadIdx.x) >> 5;
    int lane = threadIdx.x & 31;
    if (gw >= nNodes) return;
    int s = __ldg(rowp + gw), e = __ldg(rowp + gw + 1);
    float acc[4] = {0.f, 0.f, 0.f, 0.f};
    const size_t lo = (size_t)lane * 4;
    int i = s;
    for (; i + 4 <= e; i += 4) {
        int n0 = __ldg(adj + i), n1 = __ldg(adj + i + 1);
        int n2 = __ldg(adj + i + 2), n3 = __ldg(adj + i + 3);
        uint2 u0 = *(const uint2*)(feat + (size_t)n0 * 128 + lo);
        uint2 u1 = *(const uint2*)(feat + (size_t)n1 * 128 + lo);
        uint2 u2 = *(const uint2*)(feat + (size_t)n2 * 128 + lo);
        uint2 u3 = *(const uint2*)(feat + (size_t)n3 * 128 + lo);
        const __half2* h0 = (const __half2*)&u0;
        const __half2* h1 = (const __half2*)&u1;
        const __half2* h2 = (const __half2*)&u2;
        const __half2* h3 = (const __half2*)&u3;
#pragma unroll
        for (int j = 0; j < 2; j++) {
            float2 f0 = __half22float2(h0[j]);
            float2 f1 = __half22float2(h1[j]);
            float2 f2 = __half22float2(h2[j]);
            float2 f3 = __half22float2(h3[j]);
            acc[2 * j]     += (f0.x + f1.x) + (f2.x + f3.x);
            acc[2 * j + 1] += (f0.y + f1.y) + (f2.y + f3.y);
        }
    }
    for (; i < e; i++) {
        int n0 = __ldg(adj + i);
        uint2 u0 = *(const uint2*)(feat + (size_t)n0 * 128 + lo);
        const __half2* h0 = (const __half2*)&u0;
#pragma unroll
        for (int j = 0; j < 2; j++) {
            float2 f0 = __half22float2(h0[j]);
            acc[2 * j]     += f0.x;
            acc[2 * j + 1] += f0.y;
        }
    }
    float inv = 1.f / fmaxf((float)(e - s), 1.f);
    __half2 o[2];
#pragma unroll
    for (int j = 0; j < 2; j++)
        o[j] = __floats2half2_rn(acc[2 * j] * inv, acc[2 * j + 1] * inv);
    *(uint2*)(out + (size_t)gw * 128 + lo) = *(uint2*)o;
}

// ---------------- fp16 HMMA GEMM machinery (ldmatrix fragments, 512 thr) ----------------
#define A_ROW_B 80
#define B_ROW_B 528
#define A_STAGE_B (128*A_ROW_B)
#define B_STAGE_B (32*B_ROW_B)
#define STAGE_B   (A_STAGE_B + B_STAGE_B)
#define GEMM1_SMEM (4*STAGE_B)
#define H2_ROW_B 528
#define H2_TILE_B (128*H2_ROW_B)
#define GEMM2_SMEM (4*STAGE_B + H2_TILE_B)

__device__ __forceinline__ void mma_f16(float* d, const uint32_t* a, const uint32_t* b) {
    asm volatile(
        "mma.sync.aligned.m16n8k16.row.col.f32.f16.f16.f32 "
        "{%0,%1,%2,%3}, {%4,%5,%6,%7}, {%8,%9}, {%0,%1,%2,%3};"
        : "+f"(d[0]), "+f"(d[1]), "+f"(d[2]), "+f"(d[3])
        : "r"(a[0]), "r"(a[1]), "r"(a[2]), "r"(a[3]), "r"(b[0]), "r"(b[1]));
}
__device__ __forceinline__ void ldm_x4(uint32_t* r, uint32_t addr) {
    asm volatile("ldmatrix.sync.aligned.m8n8.x4.shared.b16 {%0,%1,%2,%3}, [%4];"
        : "=r"(r[0]), "=r"(r[1]), "=r"(r[2]), "=r"(r[3]) : "r"(addr));
}
__device__ __forceinline__ void ldm_x4t(uint32_t* r, uint32_t addr) {
    asm volatile("ldmatrix.sync.aligned.m8n8.x4.trans.shared.b16 {%0,%1,%2,%3}, [%4];"
        : "=r"(r[0]), "=r"(r[1]), "=r"(r[2]), "=r"(r[3]) : "r"(addr));
}

// 512-thread loaders
__device__ __forceinline__ void issue_ab(uint32_t sbase, int c, int k0, int K1,
                                         const __half* A1, const __half* A2, int K2,
                                         const __half* WTk, int bm, int Nrows, int tid) {
    int slot = c & 3;
    uint32_t aoff = sbase + slot * STAGE_B;
    uint32_t boff = aoff + A_STAGE_B;
    bool inA1 = (k0 < K1);
    {   // A: 128 rows x 32 halves = 512 x 16B chunks, 1/thread
        int row = tid >> 2, seg8 = (tid & 3) * 8;
        int grow = bm + row;
        bool ok = grow < Nrows;
        int gr = ok ? grow : 0;
        const __half* src = inA1 ? A1 + (size_t)gr * K1 + k0 + seg8
                                 : A2 + (size_t)gr * K2 + (k0 - K1) + seg8;
        uint32_t dst = aoff + (uint32_t)(row * A_ROW_B + seg8 * 2);
        int sz = ok ? 16 : 0;
        asm volatile("cp.async.cg.shared.global [%0], [%1], 16, %2;"
                     :: "r"(dst), "l"(src), "r"(sz));
    }
#pragma unroll
    for (int i = 0; i < 2; i++) {   // B: 32 k-rows x 256 halves = 1024 x 16B, 2/thread
        int idx = tid + i * 512;
        int kr = idx >> 5, seg = idx & 31;
        const __half* src = WTk + (size_t)(k0 + kr) * WROW + seg * 8;
        uint32_t dst = boff + (uint32_t)(kr * B_ROW_B + seg * 16);
        asm volatile("cp.async.cg.shared.global [%0], [%1], 16;"
                     :: "r"(dst), "l"(src));
    }
    asm volatile("cp.async.commit_group;");
}

__device__ __forceinline__ void issue_b(uint32_t sbase, int c, const __half* P, int tid) {
    int slot = c & 3;
    uint32_t boff = sbase + slot * STAGE_B + A_STAGE_B;
    int k0 = c << 5;
#pragma unroll
    for (int i = 0; i < 2; i++) {
        int idx = tid + i * 512;
        int kr = idx >> 5, seg = idx & 31;
        const __half* src = P + (size_t)(k0 + kr) * WROW + seg * 8;
        uint32_t dst = boff + (uint32_t)(kr * B_ROW_B + seg * 16);
        asm volatile("cp.async.cg.shared.global [%0], [%1], 16;"
                     :: "r"(dst), "l"(src));
    }
    asm volatile("cp.async.commit_group;");
}

// warp tile 32x64: mt 0..1, acc[2][8][4]
__device__ __forceinline__ void mma_chunk(uint32_t aBase, uint32_t bBase, float acc[2][8][4]) {
#pragma unroll
    for (int s = 0; s < 2; s++) {
        uint32_t af[2][4], bf[4][4];
#pragma unroll
        for (int mt = 0; mt < 2; mt++)
            ldm_x4(af[mt], aBase + mt * (16 * A_ROW_B) + s * 32);
#pragma unroll
        for (int p = 0; p < 4; p++)
            ldm_x4t(bf[p], bBase + s * (16 * B_ROW_B) + p * 32);
#pragma unroll
        for (int mt = 0; mt < 2; mt++)
#pragma unroll
            for (int p = 0; p < 4; p++) {
                mma_f16(acc[mt][2 * p],     af[mt], &bf[p][0]);
                mma_f16(acc[mt][2 * p + 1], af[mt], &bf[p][2]);
            }
    }
}

// ---------------- layer-1 GEMM: relu epilogue (512 threads) ----------------
__global__ void __launch_bounds__(512)
gemm_sage(const __half* A1, int K1, const __half* A2, int K2,
          const __half* W, const float* bias, __half* C, int Nrows) {
    extern __shared__ char sm[];
    const int tid = threadIdx.x;
    const int wid = tid >> 5, lane = tid & 31;
    const int warpM = wid >> 2, warpN = wid & 3;   // 4 x 4
    const int lrow = lane >> 2, lcol = lane & 3;
    const int bm = blockIdx.x * 128;
    const int nch = (K1 + K2) >> 5;

    uint32_t sbase = (uint32_t)__cvta_generic_to_shared(sm);
    const uint32_t aLane = (uint32_t)((warpM * 32 + (lane & 15)) * A_ROW_B + ((lane & 16) ? 16 : 0));
    const uint32_t bLane = (uint32_t)((lane & 15) * B_ROW_B + (warpN * 64 + ((lane & 16) ? 8 : 0)) * 2);

    float acc[2][8][4];
#pragma unroll
    for (int i = 0; i < 2; i++)
#pragma unroll
        for (int j = 0; j < 8; j++)
#pragma unroll
            for (int q = 0; q < 4; q++) acc[i][j][q] = 0.f;

    issue_ab(sbase, 0, 0, K1, A1, A2, K2, W, bm, Nrows, tid);
    issue_ab(sbase, 1, 32, K1, A1, A2, K2, W, bm, Nrows, tid);
    issue_ab(sbase, 2, 64, K1, A1, A2, K2, W, bm, Nrows, tid);

    for (int c = 0; c < nch; c++) {
        asm volatile("cp.async.wait_group 2;");
        __syncthreads();
        if (c + 3 < nch) issue_ab(sbase, c + 3, (c + 3) << 5, K1, A1, A2, K2, W, bm, Nrows, tid);
        else asm volatile("cp.async.commit_group;");
        int slot = c & 3;
        mma_chunk(sbase + slot * STAGE_B + aLane,
                  sbase + slot * STAGE_B + A_STAGE_B + bLane, acc);
    }

#pragma unroll
    for (int mt = 0; mt < 2; mt++) {
        const int r0 = bm + warpM * 32 + mt * 16 + lrow;
#pragma unroll
        for (int half = 0; half < 2; half++) {
            const int row = r0 + half * 8;
            if (row >= Nrows) continue;
#pragma unroll
            for (int nt = 0; nt < 8; nt++) {
                const int col = warpN * 64 + nt * 8 + 2 * lcol;
                float vx = fmaxf(acc[mt][nt][half * 2 + 0] + __ldg(bias + col), 0.f);
                float vy = fmaxf(acc[mt][nt][half * 2 + 1] + __ldg(bias + col + 1), 0.f);
                *(__half2*)(C + (size_t)row * 256 + col) = __floats2half2_rn(vx, vy);
            }
        }
    }
}

// ---------------- layer-2 GEMM + fused projection (512 threads) ----------------
__global__ void __launch_bounds__(512)
gemm_l2p(const __half* A1, const __half* A2, const __half* W, const float* bias,
         const __half* P, __half* U, int Nrows) {
    extern __shared__ char sm[];
    const int tid = threadIdx.x;
    const int wid = tid >> 5, lane = tid & 31;
    const int warpM = wid >> 2, warpN = wid & 3;
    const int lrow = lane >> 2, lcol = lane & 3;
    const int bm = blockIdx.x * 128;
    const int K1 = HID;
    const int nch = 16;

    uint32_t sbase = (uint32_t)__cvta_generic_to_shared(sm);
    uint32_t* H2 = (uint32_t*)(sm + 4 * STAGE_B);
    const uint32_t h2base = sbase + 4 * STAGE_B;
    const uint32_t aLane = (uint32_t)((warpM * 32 + (lane & 15)) * A_ROW_B + ((lane & 16) ? 16 : 0));
    const uint32_t bLane = (uint32_t)((lane & 15) * B_ROW_B + (warpN * 64 + ((lane & 16) ? 8 : 0)) * 2);
    const uint32_t h2Lane = h2base + (uint32_t)((warpM * 32 + (lane & 15)) * H2_ROW_B + ((lane & 16) ? 16 : 0));

    float acc[2][8][4];
#pragma unroll
    for (int i = 0; i < 2; i++)
#pragma unroll
        for (int j = 0; j < 8; j++)
#pragma unroll
            for (int q = 0; q < 4; q++) acc[i][j][q] = 0.f;

    issue_ab(sbase, 0, 0, K1, A1, A2, HID, W, bm, Nrows, tid);
    issue_ab(sbase, 1, 32, K1, A1, A2, HID, W, bm, Nrows, tid);
    issue_ab(sbase, 2, 64, K1, A1, A2, HID, W, bm, Nrows, tid);

    for (int c = 0; c < nch; c++) {
        asm volatile("cp.async.wait_group 2;");
        __syncthreads();
        if (c + 3 < nch) issue_ab(sbase, c + 3, (c + 3) << 5, K1, A1, A2, HID, W, bm, Nrows, tid);
        else asm volatile("cp.async.commit_group;");
        int slot = c & 3;
        mma_chunk(sbase + slot * STAGE_B + aLane,
                  sbase + slot * STAGE_B + A_STAGE_B + bLane, acc);
    }

    // store h2 tile (bias+relu, half) into smem; re-zero acc
#pragma unroll
    for (int mt = 0; mt < 2; mt++) {
#pragma unroll
        for (int half = 0; half < 2; half++) {
            const int row = warpM * 32 + mt * 16 + lrow + half * 8;
#pragma unroll
            for (int nt = 0; nt < 8; nt++) {
                const int col2 = warpN * 32 + nt * 4 + lcol;
                const int col = 2 * col2;
                float vx = fmaxf(acc[mt][nt][half * 2 + 0] + __ldg(bias + col), 0.f);
                float vy = fmaxf(acc[mt][nt][half * 2 + 1] + __ldg(bias + col + 1), 0.f);
                __half2 hv = __floats2half2_rn(vx, vy);
                H2[row * (H2_ROW_B / 4) + col2] = *(uint32_t*)&hv;
            }
        }
    }
#pragma unroll
    for (int i = 0; i < 2; i++)
#pragma unroll
        for (int j = 0; j < 8; j++)
#pragma unroll
            for (int q = 0; q < 4; q++) acc[i][j][q] = 0.f;
    __syncthreads();

    // projection loop: u = h2 @ P
    issue_b(sbase, 0, P, tid);
    issue_b(sbase, 1, P, tid);
    issue_b(sbase, 2, P, tid);

    for (int c = 0; c < 8; c++) {
        asm volatile("cp.async.wait_group 2;");
        __syncthreads();
        if (c + 3 < 8) issue_b(sbase, c + 3, P, tid);
        else asm volatile("cp.async.commit_group;");
        int slot = c & 3;
        uint32_t bB = sbase + slot * STAGE_B + A_STAGE_B + bLane;
#pragma unroll
        for (int s = 0; s < 2; s++) {
            uint32_t af[2][4], bf[4][4];
#pragma unroll
            for (int mt = 0; mt < 2; mt++)
                ldm_x4(af[mt], h2Lane + mt * (16 * H2_ROW_B) + c * 64 + s * 32);
#pragma unroll
            for (int p = 0; p < 4; p++)
                ldm_x4t(bf[p], bB + s * (16 * B_ROW_B) + p * 32);
#pragma unroll
            for (int mt = 0; mt < 2; mt++)
#pragma unroll
                for (int p = 0; p < 4; p++) {
                    mma_f16(acc[mt][2 * p],     af[mt], &bf[p][0]);
                    mma_f16(acc[mt][2 * p + 1], af[mt], &bf[p][2]);
                }
        }
    }

#pragma unroll
    for (int mt = 0; mt < 2; mt++) {
        const int r0 = bm + warpM * 32 + mt * 16 + lrow;
#pragma unroll
        for (int half = 0; half < 2; half++) {
            const int row = r0 + half * 8;
            if (row >= Nrows) continue;
#pragma unroll
            for (int nt = 0; nt < 8; nt++) {
                const int col = warpN * 64 + nt * 8 + 2 * lcol;
                *(__half2*)(U + (size_t)row * 256 + col) =
                    __floats2half2_rn(acc[mt][nt][half * 2 + 0], acc[mt][nt][half * 2 + 1]);
            }
        }
    }
}

// ---------------- weight composition (k-major half output) ----------------
__global__ void compose_kernel(const float* __restrict__ Wd1,
                               const float* __restrict__ Wlin_s,
                               const float* __restrict__ Wlin_t,
                               const float* __restrict__ blin_s,
                               const float* __restrict__ blin_t,
                               const float* __restrict__ bd1,
                               __half* WcsT, __half* WctT, float* bdc) {
    int i = blockIdx.x;
    int m = threadIdx.x;
    float ss = 0.f, st = 0.f;
    for (int k = 0; k < HID; k++) {
        float wl = Wd1[i * 2 * HID + k];
        float wr = Wd1[i * 2 * HID + HID + k];
        ss += wl * Wlin_s[k * HID + m];
        st += wr * Wlin_t[k * HID + m];
    }
    WcsT[(size_t)m * WROW + i] = __float2half_rn(ss);
    WctT[(size_t)m * WROW + i] = __float2half_rn(st);
    if (m == 0) {
        float b = bd1[i];
        for (int k = 0; k < HID; k++) {
            b += Wd1[i * 2 * HID + k] * blin_s[k];
            b += Wd1[i * 2 * HID + HID + k] * blin_t[k];
        }
        bdc[i] = b;
    }
}

// ---------------- decoder ----------------
__global__ void decode_kernel(const __half* __restrict__ us, const __half* __restrict__ ut,
                              const int* __restrict__ ls, const int* __restrict__ ld,
                              const float4* __restrict__ bdc, const float4* __restrict__ wd2,
                              const float* __restrict__ bd2,
                              float* __restrict__ out, int EL) {
    int g = blockIdx.x * blockDim.x + threadIdx.x;
    int w = g >> 5, lane = g & 31;
    if (w >= EL) return;
    const uint4* a = (const uint4*)(us + (size_t)__ldg(ls + w) * HID);
    const uint4* b = (const uint4*)(ut + (size_t)__ldg(ld + w) * HID);
    uint4 ua = a[lane], ub = b[lane];
    float4 c0 = bdc[lane * 2], c1 = bdc[lane * 2 + 1];
    float4 w0 = wd2[lane * 2], w1 = wd2[lane * 2 + 1];
    float2 a0 = __half22float2(*(__half2*)&ua.x), b0 = __half22float2(*(__half2*)&ub.x);
    float2 a1 = __half22float2(*(__half2*)&ua.y), b1 = __half22float2(*(__half2*)&ub.y);
    float2 a2 = __half22float2(*(__half2*)&ua.z), b2 = __half22float2(*(__half2*)&ub.z);
    float2 a3 = __half22float2(*(__half2*)&ua.w), b3 = __half22float2(*(__half2*)&ub.w);
    float sum =
        fmaxf(a0.x + b0.x + c0.x, 0.f) * w0.x + fmaxf(a0.y + b0.y + c0.y, 0.f) * w0.y +
        fmaxf(a1.x + b1.x + c0.z, 0.f) * w0.z + fmaxf(a1.y + b1.y + c0.w, 0.f) * w0.w +
        fmaxf(a2.x + b2.x + c1.x, 0.f) * w1.x + fmaxf(a2.y + b2.y + c1.y, 0.f) * w1.y +
        fmaxf(a3.x + b3.x + c1.z, 0.f) * w1.z + fmaxf(a3.y + b3.y + c1.w, 0.f) * w1.w;
#pragma unroll
    for (int o = 16; o; o >>= 1) sum += __shfl_xor_sync(0xffffffffu, sum, o);
    if (lane == 0) out[w] = sum + bd2[0];
}

// ---------------- launcher (R9 schedule) ----------------
extern "C" void kernel_launch(void* const* d_in, const int* in_sizes, int n_in,
                              void* d_out, int out_size) {
    const float* x_sotu  = (const float*)d_in[0];
    const float* x_taxon = (const float*)d_in[1];
    const int*   esrc    = (const int*)d_in[2];
    const int*   edst    = (const int*)d_in[3];
    const int*   lsrc    = (const int*)d_in[4];
    const int*   ldst    = (const int*)d_in[5];
    const float* Wl1_st  = (const float*)d_in[6];
    const float* bl1_st  = (const float*)d_in[7];
    const float* Wr1_st  = (const float*)d_in[8];
    const float* Wl1_ts  = (const float*)d_in[9];
    const float* bl1_ts  = (const float*)d_in[10];
    const float* Wr1_ts  = (const float*)d_in[11];
    const float* Wl2_st  = (const float*)d_in[12];
    const float* bl2_st  = (const float*)d_in[13];
    const float* Wr2_st  = (const float*)d_in[14];
    const float* Wl2_ts  = (const float*)d_in[15];
    const float* bl2_ts  = (const float*)d_in[16];
    const float* Wr2_ts  = (const float*)d_in[17];
    const float* Wlin_s  = (const float*)d_in[18];
    const float* blin_s  = (const float*)d_in[19];
    const float* Wlin_t  = (const float*)d_in[20];
    const float* blin_t  = (const float*)d_in[21];
    const float* Wd1     = (const float*)d_in[22];
    const float* bd1     = (const float*)d_in[23];
    const float* Wd2     = (const float*)d_in[24];
    const float* bd2     = (const float*)d_in[25];
    float* out = (float*)d_out;

    float *bdc;
    __half *aggTh, *aggSh, *h1t, *h1s, *us, *ut;
    __half *xrs, *xrt, *wt1st, *wt1ts, *wt2st, *wt2ts, *wcsT, *wctT;
    int *rowT, *rowS, *curT, *curS, *adjT, *adjS;
    cudaGetSymbolAddress((void**)&aggTh, g_aggTh);
    cudaGetSymbolAddress((void**)&aggSh, g_aggSh);
    cudaGetSymbolAddress((void**)&h1t, g_h1t);
    cudaGetSymbolAddress((void**)&h1s, g_h1s);
    cudaGetSymbolAddress((void**)&us,  g_us);
    cudaGetSymbolAddress((void**)&ut,  g_ut);
    cudaGetSymbolAddress((void**)&xrs, g_xr_s);
    cudaGetSymbolAddress((void**)&xrt, g_xr_t);
    cudaGetSymbolAddress((void**)&wt1st, g_wt1_st);
    cudaGetSymbolAddress((void**)&wt1ts, g_wt1_ts);
    cudaGetSymbolAddress((void**)&wt2st, g_wt2_st);
    cudaGetSymbolAddress((void**)&wt2ts, g_wt2_ts);
    cudaGetSymbolAddress((void**)&wcsT, g_wcsT);
    cudaGetSymbolAddress((void**)&wctT, g_wctT);
    cudaGetSymbolAddress((void**)&bdc, g_bdc);
    cudaGetSymbolAddress((void**)&rowT, g_rowT);
    cudaGetSymbolAddress((void**)&rowS, g_rowS);
    cudaGetSymbolAddress((void**)&curT, g_curT);
    cudaGetSymbolAddress((void**)&curS, g_curS);
    cudaGetSymbolAddress((void**)&adjT, g_adjT);
    cudaGetSymbolAddress((void**)&adjS, g_adjS);

    static cudaStream_t s2 = nullptr, s3 = nullptr;
    static cudaEvent_t ev[12];
    static int inited = 0;
    if (!inited) {
        cudaFuncSetAttribute(gemm_sage, cudaFuncAttributeMaxDynamicSharedMemorySize, GEMM1_SMEM);
        cudaFuncSetAttribute(gemm_l2p, cudaFuncAttributeMaxDynamicSharedMemorySize, GEMM2_SMEM);
        cudaStreamCreateWithFlags(&s2, cudaStreamNonBlocking);
        cudaStreamCreateWithFlags(&s3, cudaStreamNonBlocking);
        for (int i = 0; i < 12; i++) cudaEventCreateWithFlags(&ev[i], cudaEventDisableTiming);
        inited = 1;
    }
    cudaStream_t s0 = 0;

    const int gT = (N_TAXON + 127) / 128;   // 157
    const int gS = (N_SOTU + 127) / 128;    // 782
    const unsigned wT = (N_TAXON * 32 + 255) / 256;
    const unsigned wS = (N_SOTU * 32 + 255) / 256;

    // ---- fork 1: prep on s0 || CSR on s2 ----
    cudaEventRecord(ev[0], s0);
    cudaStreamWaitEvent(s2, ev[0], 0);

    long long nxs4 = (long long)N_SOTU * DS / 4, nxt4 = (long long)N_TAXON * DT / 4;
    tohalf_dual<<<(unsigned)((nxs4 + nxt4 + 255) / 256), 256, 0, s0>>>(
        (const float4*)x_sotu, (__half2*)xrs, nxs4,
        (const float4*)x_taxon, (__half2*)xrt, nxt4);
    wt_all<<<1792, 256, 0, s0>>>(Wl1_st, Wr1_st, wt1st,
                                 Wl1_ts, Wr1_ts, wt1ts,
                                 Wl2_st, Wr2_st, wt2st,
                                 Wl2_ts, Wr2_ts, wt2ts);
    compose_kernel<<<HID, HID, 0, s0>>>(Wd1, Wlin_s, Wlin_t, blin_s, blin_t, bd1, wcsT, wctT, bdc);

    zero_dual<<<(N_SOTU + 255) / 256, 256, 0, s2>>>(curT, N_TAXON, curS, N_SOTU);
    hist_kernel<<<(NE + 255) / 256, 256, 0, s2>>>(esrc, edst, curS, curT, NE);
    scan_dual<<<2, 1024, 0, s2>>>(curT, rowT, N_TAXON, curS, rowS, N_SOTU);
    fill_kernel<<<(NE + 255) / 256, 256, 0, s2>>>(esrc, edst, rowT, curT, adjT, rowS, curS, adjS, NE);

    // ---- join, then fork 2: layer-1 taxon chain on s0 || sotu chain on s2 ----
    cudaEventRecord(ev[1], s2);
    cudaStreamWaitEvent(s0, ev[1], 0);
    cudaEventRecord(ev[2], s0);
    cudaStreamWaitEvent(s2, ev[2], 0);

    agg256_kernel<<<wT, 256, 0, s0>>>(xrs, rowT, adjT, aggTh, N_TAXON);
    gemm_sage<<<(unsigned)gT, 512, GEMM1_SMEM, s0>>>(aggTh, DS, xrt, DT, wt1st, bl1_st, h1t, N_TAXON);

    agg128_kernel<<<wS, 256, 0, s2>>>(xrt, rowS, adjS, aggSh, N_SOTU);
    gemm_sage<<<(unsigned)gS, 512, GEMM1_SMEM, s2>>>(aggSh, DT, xrs, DS, wt1ts, bl1_ts, h1s, N_SOTU);

    // ---- join (layer 2 needs both h1t and h1s), fork 3 ----
    cudaEventRecord(ev[3], s2);
    cudaStreamWaitEvent(s0, ev[3], 0);
    cudaEventRecord(ev[4], s0);
    cudaStreamWaitEvent(s2, ev[4], 0);

    agg256_kernel<<<wT, 256, 0, s0>>>(h1s, rowT, adjT, aggTh, N_TAXON);
    gemm_l2p<<<(unsigned)gT, 512, GEMM2_SMEM, s0>>>(aggTh, h1t, wt2st, bl2_st, wctT, ut, N_TAXON);

    agg256_kernel<<<wS, 256, 0, s2>>>(h1t, rowS, adjS, aggSh, N_SOTU);
    gemm_l2p<<<(unsigned)gS, 512, GEMM2_SMEM, s2>>>(aggSh, h1s, wt2ts, bl2_ts, wcsT, us, N_SOTU);

    // ---- join, decode on s0 ----
    cudaEventRecord(ev[5], s2);
    cudaStreamWaitEvent(s0, ev[5], 0);

    decode_kernel<<<(NEL * 32 + 255) / 256, 256, 0, s0>>>(
        us, ut, lsrc, ldst,
        (const float4*)bdc, (const float4*)Wd2, bd2, out, NEL);
}

// round 13
// speedup vs baseline: 1.0195x; 1.0153x over previous
#include <cuda_runtime.h>
#include <cuda_fp16.h>
#include <cstdint>

#define N_SOTU  100000
#define N_TAXON 20000
#define NE      800000
#define NEL     200000
#define DS      256
#define DT      128
#define HID     256

#define WROW 264   // halves per weight row (256 data + 8 pad), k-major

// ---------------- scratch (device globals; no allocation) ----------------
__device__ __align__(128) __half g_aggTh[(size_t)N_TAXON*HID];
__device__ __align__(128) __half g_aggSh[(size_t)N_SOTU*HID];
__device__ __align__(128) __half g_h1t[(size_t)N_TAXON*HID];
__device__ __align__(128) __half g_h1s[(size_t)N_SOTU*HID];
__device__ __align__(128) __half g_us[(size_t)N_SOTU*HID];
__device__ __align__(128) __half g_ut[(size_t)N_TAXON*HID];
__device__ __align__(128) __half g_xr_s[(size_t)N_SOTU*DS];
__device__ __align__(128) __half g_xr_t[(size_t)N_TAXON*DT];
__device__ __align__(128) __half g_wt1_st[384*WROW];
__device__ __align__(128) __half g_wt1_ts[384*WROW];
__device__ __align__(128) __half g_wt2_st[512*WROW];
__device__ __align__(128) __half g_wt2_ts[512*WROW];
__device__ __align__(128) __half g_wcsT[256*WROW];
__device__ __align__(128) __half g_wctT[256*WROW];
__device__ __align__(128) float  g_bdc[256];
// CSR
__device__ int g_rowT[N_TAXON + 1];
__device__ int g_rowS[N_SOTU + 1];
__device__ int g_curT[N_TAXON];
__device__ int g_curS[N_SOTU];
__device__ int g_adjT[NE];
__device__ int g_adjS[NE];

// ---------------- prep kernels ----------------
__global__ void tohalf_dual(const float4* inA, __half2* outA, long long nA4,
                            const float4* inB, __half2* outB, long long nB4) {
    long long i = blockIdx.x * (long long)blockDim.x + threadIdx.x;
    const float4* in; __half2* out; long long idx;
    if (i < nA4) { in = inA; out = outA; idx = i; }
    else if (i - nA4 < nB4) { in = inB; out = outB; idx = i - nA4; }
    else return;
    float4 v = in[idx];
    out[idx * 2 + 0] = __floats2half2_rn(v.x, v.y);
    out[idx * 2 + 1] = __floats2half2_rn(v.z, v.w);
}

__global__ void wt_all(const float* W1a, const float* W2a, __half* Oa,
                       const float* W1b, const float* W2b, __half* Ob,
                       const float* W1c, const float* W2c, __half* Oc,
                       const float* W1d, const float* W2d, __half* Od) {
    int b = blockIdx.x, h = threadIdx.x;
    const float* W1; const float* W2; __half* O; int K1, K2, k;
    if (b < 384)        { W1 = W1a; W2 = W2a; O = Oa; K1 = 256; K2 = 128; k = b; }
    else if (b < 768)   { W1 = W1b; W2 = W2b; O = Ob; K1 = 128; K2 = 256; k = b - 384; }
    else if (b < 1280)  { W1 = W1c; W2 = W2c; O = Oc; K1 = 256; K2 = 256; k = b - 768; }
    else                { W1 = W1d; W2 = W2d; O = Od; K1 = 256; K2 = 256; k = b - 1280; }
    float v = (k < K1) ? W1[h * K1 + k] : W2[h * K2 + (k - K1)];
    O[(size_t)k * WROW + h] = __float2half_rn(v);
}

// ---------------- CSR build ----------------
__global__ void zero_dual(int* a, int na, int* b, int nb) {
    int i = blockIdx.x * blockDim.x + threadIdx.x;
    if (i < na) a[i] = 0;
    if (i < nb) b[i] = 0;
}

// 2 edges per thread (NE even)
__global__ void hist_kernel(const int2* __restrict__ src2, const int2* __restrict__ dst2,
                            int* curS, int* curT, int E2) {
    int e = blockIdx.x * blockDim.x + threadIdx.x;
    if (e >= E2) return;
    int2 s = __ldg(src2 + e), d = __ldg(dst2 + e);
    atomicAdd(curT + d.x, 1);
    atomicAdd(curT + d.y, 1);
    atomicAdd(curS + s.x, 1);
    atomicAdd(curS + s.y, 1);
}

__global__ void __launch_bounds__(1024)
scan_dual(int* cntA, int* rowA, int nA, int* cntB, int* rowB, int nB) {
    int* cnt = blockIdx.x ? cntB : cntA;
    int* row = blockIdx.x ? rowB : rowA;
    int n = blockIdx.x ? nB : nA;
    __shared__ int wsum[32];
    __shared__ int carry;
    int tid = threadIdx.x, lane = tid & 31, wid = tid >> 5;
    if (tid == 0) carry = 0;
    __syncthreads();
    for (int base = 0; base < n; base += 1024) {
        int v = (base + tid < n) ? cnt[base + tid] : 0;
        int x = v;
#pragma unroll
        for (int o = 1; o < 32; o <<= 1) {
            int t = __shfl_up_sync(0xffffffffu, x, o);
            if (lane >= o) x += t;
        }
        if (lane == 31) wsum[wid] = x;
        __syncthreads();
        if (wid == 0) {
            int y = wsum[lane];
#pragma unroll
            for (int o = 1; o < 32; o <<= 1) {
                int t = __shfl_up_sync(0xffffffffu, y, o);
                if (lane >= o) y += t;
            }
            wsum[lane] = y;
        }
        __syncthreads();
        int incl = x + (wid ? wsum[wid - 1] : 0) + carry;
        if (base + tid < n) { row[base + tid] = incl - v; cnt[base + tid] = 0; }
        __syncthreads();
        if (tid == 1023) carry = incl;
        __syncthreads();
    }
    if (tid == 0) row[n] = carry;
}

// 2 edges per thread
__global__ void fill_kernel(const int2* __restrict__ src2, const int2* __restrict__ dst2,
                            const int* __restrict__ rowT, int* curT, int* adjT,
                            const int* __restrict__ rowS, int* curS, int* adjS, int E2) {
    int e = blockIdx.x * blockDim.x + threadIdx.x;
    if (e >= E2) return;
    int2 s = __ldg(src2 + e), d = __ldg(dst2 + e);
    adjT[__ldg(rowT + d.x) + atomicAdd(curT + d.x, 1)] = s.x;
    adjS[__ldg(rowS + s.x) + atomicAdd(curS + s.x, 1)] = d.x;
    adjT[__ldg(rowT + d.y) + atomicAdd(curT + d.y, 1)] = s.y;
    adjS[__ldg(rowS + s.y) + atomicAdd(curS + s.y, 1)] = d.y;
}

// ---------------- warp-per-node mean aggregation ----------------
// 256-wide, unroll x8 (avg sotu degree = 8 -> 8 in-flight loads covers L2 latency)
__global__ void agg256_kernel(const __half* __restrict__ feat,
                              const int* __restrict__ rowp,
                              const int* __restrict__ adj,
                              __half* __restrict__ out, int nNodes) {
    int gw = (blockIdx.x * blockDim.x + threadIdx.x) >> 5;
    int lane = threadIdx.x & 31;
    if (gw >= nNodes) return;
    int s = __ldg(rowp + gw), e = __ldg(rowp + gw + 1);
    float acc[8] = {0.f, 0.f, 0.f, 0.f, 0.f, 0.f, 0.f, 0.f};
    const size_t lo = (size_t)lane * 8;
    int i = s;
    for (; i + 8 <= e; i += 8) {
        int nn[8];
#pragma unroll
        for (int q = 0; q < 8; q++) nn[q] = __ldg(adj + i + q);
        uint4 u[8];
#pragma unroll
        for (int q = 0; q < 8; q++) u[q] = *(const uint4*)(feat + (size_t)nn[q] * 256 + lo);
#pragma unroll
        for (int q = 0; q < 8; q++) {
            const __half2* h = (const __half2*)&u[q];
#pragma unroll
            for (int j = 0; j < 4; j++) {
                float2 f = __half22float2(h[j]);
                acc[2 * j]     += f.x;
                acc[2 * j + 1] += f.y;
            }
        }
    }
    for (; i + 4 <= e; i += 4) {
        int nn[4];
#pragma unroll
        for (int q = 0; q < 4; q++) nn[q] = __ldg(adj + i + q);
        uint4 u[4];
#pragma unroll
        for (int q = 0; q < 4; q++) u[q] = *(const uint4*)(feat + (size_t)nn[q] * 256 + lo);
#pragma unroll
        for (int q = 0; q < 4; q++) {
            const __half2* h = (const __half2*)&u[q];
#pragma unroll
            for (int j = 0; j < 4; j++) {
                float2 f = __half22float2(h[j]);
                acc[2 * j]     += f.x;
                acc[2 * j + 1] += f.y;
            }
        }
    }
    for (; i < e; i++) {
        int n0 = __ldg(adj + i);
        uint4 u0 = *(const uint4*)(feat + (size_t)n0 * 256 + lo);
        const __half2* h0 = (const __half2*)&u0;
#pragma unroll
        for (int j = 0; j < 4; j++) {
            float2 f0 = __half22float2(h0[j]);
            acc[2 * j]     += f0.x;
            acc[2 * j + 1] += f0.y;
        }
    }
    float inv = 1.f / fmaxf((float)(e - s), 1.f);
    __half2 o[4];
#pragma unroll
    for (int j = 0; j < 4; j++)
        o[j] = __floats2half2_rn(acc[2 * j] * inv, acc[2 * j + 1] * inv);
    *(uint4*)(out + (size_t)gw * 256 + lo) = *(uint4*)o;
}

// 128-wide, unroll x8
__global__ void agg128_kernel(const __half* __restrict__ feat,
                              const int* __restrict__ rowp,
                              const int* __restrict__ adj,
                              __half* __restrict__ out, int nNodes) {
    int gw = (blockIdx.x * blockDim.x + threadIdx.x) >> 5;
    int lane = threadIdx.x & 31;
    if (gw >= nNodes) return;
    int s = __ldg(rowp + gw), e = __ldg(rowp + gw + 1);
    float acc[4] = {0.f, 0.f, 0.f, 0.f};
    const size_t lo = (size_t)lane * 4;
    int i = s;
    for (; i + 8 <= e; i += 8) {
        int nn[8];
#pragma unroll
        for (int q = 0; q < 8; q++) nn[q] = __ldg(adj + i + q);
        uint2 u[8];
#pragma unroll
        for (int q = 0; q < 8; q++) u[q] = *(const uint2*)(feat + (size_t)nn[q] * 128 + lo);
#pragma unroll
        for (int q = 0; q < 8; q++) {
            const __half2* h = (const __half2*)&u[q];
#pragma unroll
            for (int j = 0; j < 2; j++) {
                float2 f = __half22float2(h[j]);
                acc[2 * j]     += f.x;
                acc[2 * j + 1] += f.y;
            }
        }
    }
    for (; i + 4 <= e; i += 4) {
        int nn[4];
#pragma unroll
        for (int q = 0; q < 4; q++) nn[q] = __ldg(adj + i + q);
        uint2 u[4];
#pragma unroll
        for (int q = 0; q < 4; q++) u[q] = *(const uint2*)(feat + (size_t)nn[q] * 128 + lo);
#pragma unroll
        for (int q = 0; q < 4; q++) {
            const __half2* h = (const __half2*)&u[q];
#pragma unroll
            for (int j = 0; j < 2; j++) {
                float2 f = __half22float2(h[j]);
                acc[2 * j]     += f.x;
                acc[2 * j + 1] += f.y;
            }
        }
    }
    for (; i < e; i++) {
        int n0 = __ldg(adj + i);
        uint2 u0 = *(const uint2*)(feat + (size_t)n0 * 128 + lo);
        const __half2* h0 = (const __half2*)&u0;
#pragma unroll
        for (int j = 0; j < 2; j++) {
            float2 f0 = __half22float2(h0[j]);
            acc[2 * j]     += f0.x;
            acc[2 * j + 1] += f0.y;
        }
    }
    float inv = 1.f / fmaxf((float)(e - s), 1.f);
    __half2 o[2];
#pragma unroll
    for (int j = 0; j < 2; j++)
        o[j] = __floats2half2_rn(acc[2 * j] * inv, acc[2 * j + 1] * inv);
    *(uint2*)(out + (size_t)gw * 128 + lo) = *(uint2*)o;
}

// ---------------- fp16 HMMA GEMM machinery (ldmatrix fragments, R9 config) ----------------
#define A_ROW_B 80
#define B_ROW_B 528
#define A_STAGE_B (128*A_ROW_B)
#define B_STAGE_B (32*B_ROW_B)
#define STAGE_B   (A_STAGE_B + B_STAGE_B)
#define GEMM1_SMEM (4*STAGE_B)
#define H2_ROW_B 528
#define H2_TILE_B (128*H2_ROW_B)
#define GEMM2_SMEM (4*STAGE_B + H2_TILE_B)

__device__ __forceinline__ void mma_f16(float* d, const uint32_t* a, const uint32_t* b) {
    asm volatile(
        "mma.sync.aligned.m16n8k16.row.col.f32.f16.f16.f32 "
        "{%0,%1,%2,%3}, {%4,%5,%6,%7}, {%8,%9}, {%0,%1,%2,%3};"
        : "+f"(d[0]), "+f"(d[1]), "+f"(d[2]), "+f"(d[3])
        : "r"(a[0]), "r"(a[1]), "r"(a[2]), "r"(a[3]), "r"(b[0]), "r"(b[1]));
}
__device__ __forceinline__ void ldm_x4(uint32_t* r, uint32_t addr) {
    asm volatile("ldmatrix.sync.aligned.m8n8.x4.shared.b16 {%0,%1,%2,%3}, [%4];"
        : "=r"(r[0]), "=r"(r[1]), "=r"(r[2]), "=r"(r[3]) : "r"(addr));
}
__device__ __forceinline__ void ldm_x4t(uint32_t* r, uint32_t addr) {
    asm volatile("ldmatrix.sync.aligned.m8n8.x4.trans.shared.b16 {%0,%1,%2,%3}, [%4];"
        : "=r"(r[0]), "=r"(r[1]), "=r"(r[2]), "=r"(r[3]) : "r"(addr));
}

__device__ __forceinline__ void issue_ab(uint32_t sbase, int c, int k0, int K1,
                                         const __half* A1, const __half* A2, int K2,
                                         const __half* WTk, int bm, int Nrows, int tid) {
    int slot = c & 3;
    uint32_t aoff = sbase + slot * STAGE_B;
    uint32_t boff = aoff + A_STAGE_B;
    bool inA1 = (k0 < K1);
#pragma unroll
    for (int i = 0; i < 2; i++) {
        int idx = tid + i * 256;
        int row = idx >> 2, seg8 = (idx & 3) * 8;
        int grow = bm + row;
        bool ok = grow < Nrows;
        int gr = ok ? grow : 0;
        const __half* src = inA1 ? A1 + (size_t)gr * K1 + k0 + seg8
                                 : A2 + (size_t)gr * K2 + (k0 - K1) + seg8;
        uint32_t dst = aoff + (uint32_t)(row * A_ROW_B + seg8 * 2);
        int sz = ok ? 16 : 0;
        asm volatile("cp.async.cg.shared.global [%0], [%1], 16, %2;"
                     :: "r"(dst), "l"(src), "r"(sz));
    }
#pragma unroll
    for (int i = 0; i < 4; i++) {
        int idx = tid + i * 256;
        int kr = idx >> 5, seg = idx & 31;
        const __half* src = WTk + (size_t)(k0 + kr) * WROW + seg * 8;
        uint32_t dst = boff + (uint32_t)(kr * B_ROW_B + seg * 16);
        asm volatile("cp.async.cg.shared.global [%0], [%1], 16;"
                     :: "r"(dst), "l"(src));
    }
    asm volatile("cp.async.commit_group;");
}

__device__ __forceinline__ void issue_b(uint32_t sbase, int c, const __half* P, int tid) {
    int slot = c & 3;
    uint32_t boff = sbase + slot * STAGE_B + A_STAGE_B;
    int k0 = c << 5;
#pragma unroll
    for (int i = 0; i < 4; i++) {
        int idx = tid + i * 256;
        int kr = idx >> 5, seg = idx & 31;
        const __half* src = P + (size_t)(k0 + kr) * WROW + seg * 8;
        uint32_t dst = boff + (uint32_t)(kr * B_ROW_B + seg * 16);
        asm volatile("cp.async.cg.shared.global [%0], [%1], 16;"
                     :: "r"(dst), "l"(src));
    }
    asm volatile("cp.async.commit_group;");
}

__device__ __forceinline__ void mma_chunk(uint32_t aBase, uint32_t bBase, float acc[4][8][4]) {
#pragma unroll
    for (int s = 0; s < 2; s++) {
        uint32_t af[4][4], bf[4][4];
#pragma unroll
        for (int mt = 0; mt < 4; mt++)
            ldm_x4(af[mt], aBase + mt * (16 * A_ROW_B) + s * 32);
#pragma unroll
        for (int p = 0; p < 4; p++)
            ldm_x4t(bf[p], bBase + s * (16 * B_ROW_B) + p * 32);
#pragma unroll
        for (int mt = 0; mt < 4; mt++)
#pragma unroll
            for (int p = 0; p < 4; p++) {
                mma_f16(acc[mt][2 * p],     af[mt], &bf[p][0]);
                mma_f16(acc[mt][2 * p + 1], af[mt], &bf[p][2]);
            }
    }
}

// ---------------- layer-1 GEMM: relu epilogue (R9: 256 threads) ----------------
__global__ void __launch_bounds__(256)
gemm_sage(const __half* A1, int K1, const __half* A2, int K2,
          const __half* W, const float* bias, __half* C, int Nrows) {
    extern __shared__ char sm[];
    const int tid = threadIdx.x;
    const int wid = tid >> 5, lane = tid & 31;
    const int warpM = wid >> 2, warpN = wid & 3;
    const int lrow = lane >> 2, lcol = lane & 3;
    const int bm = blockIdx.x * 128;
    const int nch = (K1 + K2) >> 5;

    uint32_t sbase = (uint32_t)__cvta_generic_to_shared(sm);
    const uint32_t aLane = (uint32_t)((warpM * 64 + (lane & 15)) * A_ROW_B + ((lane & 16) ? 16 : 0));
    const uint32_t bLane = (uint32_t)((lane & 15) * B_ROW_B + (warpN * 64 + ((lane & 16) ? 8 : 0)) * 2);

    float2 bv[8];
#pragma unroll
    for (int nt = 0; nt < 8; nt++) {
        int col = warpN * 64 + nt * 8 + 2 * lcol;
        bv[nt].x = __ldg(bias + col); bv[nt].y = __ldg(bias + col + 1);
    }

    float acc[4][8][4];
#pragma unroll
    for (int i = 0; i < 4; i++)
#pragma unroll
        for (int j = 0; j < 8; j++)
#pragma unroll
            for (int q = 0; q < 4; q++) acc[i][j][q] = 0.f;

    issue_ab(sbase, 0, 0, K1, A1, A2, K2, W, bm, Nrows, tid);
    issue_ab(sbase, 1, 32, K1, A1, A2, K2, W, bm, Nrows, tid);
    issue_ab(sbase, 2, 64, K1, A1, A2, K2, W, bm, Nrows, tid);

    for (int c = 0; c < nch; c++) {
        asm volatile("cp.async.wait_group 2;");
        __syncthreads();
        if (c + 3 < nch) issue_ab(sbase, c + 3, (c + 3) << 5, K1, A1, A2, K2, W, bm, Nrows, tid);
        else asm volatile("cp.async.commit_group;");
        int slot = c & 3;
        mma_chunk(sbase + slot * STAGE_B + aLane,
                  sbase + slot * STAGE_B + A_STAGE_B + bLane, acc);
    }

#pragma unroll
    for (int mt = 0; mt < 4; mt++) {
        const int r0 = bm + warpM * 64 + mt * 16 + lrow;
#pragma unroll
        for (int half = 0; half < 2; half++) {
            const int row = r0 + half * 8;
            if (row >= Nrows) continue;
#pragma unroll
            for (int nt = 0; nt < 8; nt++) {
                const int col = warpN * 64 + nt * 8 + 2 * lcol;
                float vx = fmaxf(acc[mt][nt][half * 2 + 0] + bv[nt].x, 0.f);
                float vy = fmaxf(acc[mt][nt][half * 2 + 1] + bv[nt].y, 0.f);
                *(__half2*)(C + (size_t)row * 256 + col) = __floats2half2_rn(vx, vy);
            }
        }
    }
}

// ---------------- layer-2 GEMM + fused projection (R9: 256 threads) ----------------
__global__ void __launch_bounds__(256)
gemm_l2p(const __half* A1, const __half* A2, const __half* W, const float* bias,
         const __half* P, __half* U, int Nrows) {
    extern __shared__ char sm[];
    const int tid = threadIdx.x;
    const int wid = tid >> 5, lane = tid & 31;
    const int warpM = wid >> 2, warpN = wid & 3;
    const int lrow = lane >> 2, lcol = lane & 3;
    const int bm = blockIdx.x * 128;
    const int K1 = HID;
    const int nch = 16;

    uint32_t sbase = (uint32_t)__cvta_generic_to_shared(sm);
    uint32_t* H2 = (uint32_t*)(sm + 4 * STAGE_B);
    const uint32_t h2base = sbase + 4 * STAGE_B;
    const uint32_t aLane = (uint32_t)((warpM * 64 + (lane & 15)) * A_ROW_B + ((lane & 16) ? 16 : 0));
    const uint32_t bLane = (uint32_t)((lane & 15) * B_ROW_B + (warpN * 64 + ((lane & 16) ? 8 : 0)) * 2);
    const uint32_t h2Lane = h2base + (uint32_t)((warpM * 64 + (lane & 15)) * H2_ROW_B + ((lane & 16) ? 16 : 0));

    float2 bv[8];
#pragma unroll
    for (int nt = 0; nt < 8; nt++) {
        int col = warpN * 64 + nt * 8 + 2 * lcol;
        bv[nt].x = __ldg(bias + col); bv[nt].y = __ldg(bias + col + 1);
    }

    float acc[4][8][4];
#pragma unroll
    for (int i = 0; i < 4; i++)
#pragma unroll
        for (int j = 0; j < 8; j++)
#pragma unroll
            for (int q = 0; q < 4; q++) acc[i][j][q] = 0.f;

    issue_ab(sbase, 0, 0, K1, A1, A2, HID, W, bm, Nrows, tid);
    issue_ab(sbase, 1, 32, K1, A1, A2, HID, W, bm, Nrows, tid);
    issue_ab(sbase, 2, 64, K1, A1, A2, HID, W, bm, Nrows, tid);

    for (int c = 0; c < nch; c++) {
        asm volatile("cp.async.wait_group 2;");
        __syncthreads();
        if (c + 3 < nch) issue_ab(sbase, c + 3, (c + 3) << 5, K1, A1, A2, HID, W, bm, Nrows, tid);
        else asm volatile("cp.async.commit_group;");
        int slot = c & 3;
        mma_chunk(sbase + slot * STAGE_B + aLane,
                  sbase + slot * STAGE_B + A_STAGE_B + bLane, acc);
    }

    // store h2 tile (bias+relu, half) into smem; re-zero acc
#pragma unroll
    for (int mt = 0; mt < 4; mt++) {
#pragma unroll
        for (int half = 0; half < 2; half++) {
            const int row = warpM * 64 + mt * 16 + lrow + half * 8;
#pragma unroll
            for (int nt = 0; nt < 8; nt++) {
                const int col2 = warpN * 32 + nt * 4 + lcol;
                float vx = fmaxf(acc[mt][nt][half * 2 + 0] + bv[nt].x, 0.f);
                float vy = fmaxf(acc[mt][nt][half * 2 + 1] + bv[nt].y, 0.f);
                __half2 hv = __floats2half2_rn(vx, vy);
                H2[row * (H2_ROW_B / 4) + col2] = *(uint32_t*)&hv;
            }
        }
    }
#pragma unroll
    for (int i = 0; i < 4; i++)
#pragma unroll
        for (int j = 0; j < 8; j++)
#pragma unroll
            for (int q = 0; q < 4; q++) acc[i][j][q] = 0.f;
    __syncthreads();

    // projection loop: u = h2 @ P
    issue_b(sbase, 0, P, tid);
    issue_b(sbase, 1, P, tid);
    issue_b(sbase, 2, P, tid);

    for (int c = 0; c < 8; c++) {
        asm volatile("cp.async.wait_group 2;");
        __syncthreads();
        if (c + 3 < 8) issue_b(sbase, c + 3, P, tid);
        else asm volatile("cp.async.commit_group;");
        int slot = c & 3;
        uint32_t bB = sbase + slot * STAGE_B + A_STAGE_B + bLane;
#pragma unroll
        for (int s = 0; s < 2; s++) {
            uint32_t af[4][4], bf[4][4];
#pragma unroll
            for (int mt = 0; mt < 4; mt++)
                ldm_x4(af[mt], h2Lane + mt * (16 * H2_ROW_B) + c * 64 + s * 32);
#pragma unroll
            for (int p = 0; p < 4; p++)
                ldm_x4t(bf[p], bB + s * (16 * B_ROW_B) + p * 32);
#pragma unroll
            for (int mt = 0; mt < 4; mt++)
#pragma unroll
                for (int p = 0; p < 4; p++) {
                    mma_f16(acc[mt][2 * p],     af[mt], &bf[p][0]);
                    mma_f16(acc[mt][2 * p + 1], af[mt], &bf[p][2]);
                }
        }
    }

#pragma unroll
    for (int mt = 0; mt < 4; mt++) {
        const int r0 = bm + warpM * 64 + mt * 16 + lrow;
#pragma unroll
        for (int half = 0; half < 2; half++) {
            const int row = r0 + half * 8;
            if (row >= Nrows) continue;
#pragma unroll
            for (int nt = 0; nt < 8; nt++) {
                const int col = warpN * 64 + nt * 8 + 2 * lcol;
                *(__half2*)(U + (size_t)row * 256 + col) =
                    __floats2half2_rn(acc[mt][nt][half * 2 + 0], acc[mt][nt][half * 2 + 1]);
            }
        }
    }
}

// ---------------- weight composition (k-major half output) ----------------
__global__ void compose_kernel(const float* __restrict__ Wd1,
                               const float* __restrict__ Wlin_s,
                               const float* __restrict__ Wlin_t,
                               const float* __restrict__ blin_s,
                               const float* __restrict__ blin_t,
                               const float* __restrict__ bd1,
                               __half* WcsT, __half* WctT, float* bdc) {
    int i = blockIdx.x;
    int m = threadIdx.x;
    float ss = 0.f, st = 0.f;
    for (int k = 0; k < HID; k++) {
        float wl = Wd1[i * 2 * HID + k];
        float wr = Wd1[i * 2 * HID + HID + k];
        ss += wl * Wlin_s[k * HID + m];
        st += wr * Wlin_t[k * HID + m];
    }
    WcsT[(size_t)m * WROW + i] = __float2half_rn(ss);
    WctT[(size_t)m * WROW + i] = __float2half_rn(st);
    if (m == 0) {
        float b = bd1[i];
        for (int k = 0; k < HID; k++) {
            b += Wd1[i * 2 * HID + k] * blin_s[k];
            b += Wd1[i * 2 * HID + HID + k] * blin_t[k];
        }
        bdc[i] = b;
    }
}

// ---------------- decoder ----------------
__global__ void decode_kernel(const __half* __restrict__ us, const __half* __restrict__ ut,
                              const int* __restrict__ ls, const int* __restrict__ ld,
                              const float4* __restrict__ bdc, const float4* __restrict__ wd2,
                              const float* __restrict__ bd2,
                              float* __restrict__ out, int EL) {
    int g = blockIdx.x * blockDim.x + threadIdx.x;
    int w = g >> 5, lane = g & 31;
    if (w >= EL) return;
    const uint4* a = (const uint4*)(us + (size_t)__ldg(ls + w) * HID);
    const uint4* b = (const uint4*)(ut + (size_t)__ldg(ld + w) * HID);
    uint4 ua = a[lane], ub = b[lane];
    float4 c0 = bdc[lane * 2], c1 = bdc[lane * 2 + 1];
    float4 w0 = wd2[lane * 2], w1 = wd2[lane * 2 + 1];
    float2 a0 = __half22float2(*(__half2*)&ua.x), b0 = __half22float2(*(__half2*)&ub.x);
    float2 a1 = __half22float2(*(__half2*)&ua.y), b1 = __half22float2(*(__half2*)&ub.y);
    float2 a2 = __half22float2(*(__half2*)&ua.z), b2 = __half22float2(*(__half2*)&ub.z);
    float2 a3 = __half22float2(*(__half2*)&ua.w), b3 = __half22float2(*(__half2*)&ub.w);
    float sum =
        fmaxf(a0.x + b0.x + c0.x, 0.f) * w0.x + fmaxf(a0.y + b0.y + c0.y, 0.f) * w0.y +
        fmaxf(a1.x + b1.x + c0.z, 0.f) * w0.z + fmaxf(a1.y + b1.y + c0.w, 0.f) * w0.w +
        fmaxf(a2.x + b2.x + c1.x, 0.f) * w1.x + fmaxf(a2.y + b2.y + c1.y, 0.f) * w1.y +
        fmaxf(a3.x + b3.x + c1.z, 0.f) * w1.z + fmaxf(a3.y + b3.y + c1.w, 0.f) * w1.w;
#pragma unroll
    for (int o = 16; o; o >>= 1) sum += __shfl_xor_sync(0xffffffffu, sum, o);
    if (lane == 0) out[w] = sum + bd2[0];
}

// ---------------- launcher (R9 schedule) ----------------
extern "C" void kernel_launch(void* const* d_in, const int* in_sizes, int n_in,
                              void* d_out, int out_size) {
    const float* x_sotu  = (const float*)d_in[0];
    const float* x_taxon = (const float*)d_in[1];
    const int*   esrc    = (const int*)d_in[2];
    const int*   edst    = (const int*)d_in[3];
    const int*   lsrc    = (const int*)d_in[4];
    const int*   ldst    = (const int*)d_in[5];
    const float* Wl1_st  = (const float*)d_in[6];
    const float* bl1_st  = (const float*)d_in[7];
    const float* Wr1_st  = (const float*)d_in[8];
    const float* Wl1_ts  = (const float*)d_in[9];
    const float* bl1_ts  = (const float*)d_in[10];
    const float* Wr1_ts  = (const float*)d_in[11];
    const float* Wl2_st  = (const float*)d_in[12];
    const float* bl2_st  = (const float*)d_in[13];
    const float* Wr2_st  = (const float*)d_in[14];
    const float* Wl2_ts  = (const float*)d_in[15];
    const float* bl2_ts  = (const float*)d_in[16];
    const float* Wr2_ts  = (const float*)d_in[17];
    const float* Wlin_s  = (const float*)d_in[18];
    const float* blin_s  = (const float*)d_in[19];
    const float* Wlin_t  = (const float*)d_in[20];
    const float* blin_t  = (const float*)d_in[21];
    const float* Wd1     = (const float*)d_in[22];
    const float* bd1     = (const float*)d_in[23];
    const float* Wd2     = (const float*)d_in[24];
    const float* bd2     = (const float*)d_in[25];
    float* out = (float*)d_out;

    float *bdc;
    __half *aggTh, *aggSh, *h1t, *h1s, *us, *ut;
    __half *xrs, *xrt, *wt1st, *wt1ts, *wt2st, *wt2ts, *wcsT, *wctT;
    int *rowT, *rowS, *curT, *curS, *adjT, *adjS;
    cudaGetSymbolAddress((void**)&aggTh, g_aggTh);
    cudaGetSymbolAddress((void**)&aggSh, g_aggSh);
    cudaGetSymbolAddress((void**)&h1t, g_h1t);
    cudaGetSymbolAddress((void**)&h1s, g_h1s);
    cudaGetSymbolAddress((void**)&us,  g_us);
    cudaGetSymbolAddress((void**)&ut,  g_ut);
    cudaGetSymbolAddress((void**)&xrs, g_xr_s);
    cudaGetSymbolAddress((void**)&xrt, g_xr_t);
    cudaGetSymbolAddress((void**)&wt1st, g_wt1_st);
    cudaGetSymbolAddress((void**)&wt1ts, g_wt1_ts);
    cudaGetSymbolAddress((void**)&wt2st, g_wt2_st);
    cudaGetSymbolAddress((void**)&wt2ts, g_wt2_ts);
    cudaGetSymbolAddress((void**)&wcsT, g_wcsT);
    cudaGetSymbolAddress((void**)&wctT, g_wctT);
    cudaGetSymbolAddress((void**)&bdc, g_bdc);
    cudaGetSymbolAddress((void**)&rowT, g_rowT);
    cudaGetSymbolAddress((void**)&rowS, g_rowS);
    cudaGetSymbolAddress((void**)&curT, g_curT);
    cudaGetSymbolAddress((void**)&curS, g_curS);
    cudaGetSymbolAddress((void**)&adjT, g_adjT);
    cudaGetSymbolAddress((void**)&adjS, g_adjS);

    static cudaStream_t s2 = nullptr;
    static cudaEvent_t ev[8];
    static int inited = 0;
    if (!inited) {
        cudaFuncSetAttribute(gemm_sage, cudaFuncAttributeMaxDynamicSharedMemorySize, GEMM1_SMEM);
        cudaFuncSetAttribute(gemm_l2p, cudaFuncAttributeMaxDynamicSharedMemorySize, GEMM2_SMEM);
        cudaStreamCreateWithFlags(&s2, cudaStreamNonBlocking);
        for (int i = 0; i < 8; i++) cudaEventCreateWithFlags(&ev[i], cudaEventDisableTiming);
        inited = 1;
    }
    cudaStream_t s0 = 0;

    const int gT = (N_TAXON + 127) / 128;   // 157
    const int gS = (N_SOTU + 127) / 128;    // 782
    const unsigned wT = (N_TAXON * 32 + 255) / 256;
    const unsigned wS = (N_SOTU * 32 + 255) / 256;

    // ---- fork 1: prep on s0 || CSR on s2 ----
    cudaEventRecord(ev[0], s0);
    cudaStreamWaitEvent(s2, ev[0], 0);

    long long nxs4 = (long long)N_SOTU * DS / 4, nxt4 = (long long)N_TAXON * DT / 4;
    tohalf_dual<<<(unsigned)((nxs4 + nxt4 + 255) / 256), 256, 0, s0>>>(
        (const float4*)x_sotu, (__half2*)xrs, nxs4,
        (const float4*)x_taxon, (__half2*)xrt, nxt4);
    wt_all<<<1792, 256, 0, s0>>>(Wl1_st, Wr1_st, wt1st,
                                 Wl1_ts, Wr1_ts, wt1ts,
                                 Wl2_st, Wr2_st, wt2st,
                                 Wl2_ts, Wr2_ts, wt2ts);
    compose_kernel<<<HID, HID, 0, s0>>>(Wd1, Wlin_s, Wlin_t, blin_s, blin_t, bd1, wcsT, wctT, bdc);

    zero_dual<<<(N_SOTU + 255) / 256, 256, 0, s2>>>(curT, N_TAXON, curS, N_SOTU);
    hist_kernel<<<(NE / 2 + 255) / 256, 256, 0, s2>>>(
        (const int2*)esrc, (const int2*)edst, curS, curT, NE / 2);
    scan_dual<<<2, 1024, 0, s2>>>(curT, rowT, N_TAXON, curS, rowS, N_SOTU);
    fill_kernel<<<(NE / 2 + 255) / 256, 256, 0, s2>>>(
        (const int2*)esrc, (const int2*)edst, rowT, curT, adjT, rowS, curS, adjS, NE / 2);

    // ---- join, then fork 2: layer-1 taxon chain on s0 || sotu chain on s2 ----
    cudaEventRecord(ev[1], s2);
    cudaStreamWaitEvent(s0, ev[1], 0);
    cudaEventRecord(ev[2], s0);
    cudaStreamWaitEvent(s2, ev[2], 0);

    agg256_kernel<<<wT, 256, 0, s0>>>(xrs, rowT, adjT, aggTh, N_TAXON);
    gemm_sage<<<(unsigned)gT, 256, GEMM1_SMEM, s0>>>(aggTh, DS, xrt, DT, wt1st, bl1_st, h1t, N_TAXON);

    agg128_kernel<<<wS, 256, 0, s2>>>(xrt, rowS, adjS, aggSh, N_SOTU);
    gemm_sage<<<(unsigned)gS, 256, GEMM1_SMEM, s2>>>(aggSh, DT, xrs, DS, wt1ts, bl1_ts, h1s, N_SOTU);

    // ---- join (layer 2 needs both h1t and h1s), fork 3 ----
    cudaEventRecord(ev[3], s2);
    cudaStreamWaitEvent(s0, ev[3], 0);
    cudaEventRecord(ev[4], s0);
    cudaStreamWaitEvent(s2, ev[4], 0);

    agg256_kernel<<<wT, 256, 0, s0>>>(h1s, rowT, adjT, aggTh, N_TAXON);
    gemm_l2p<<<(unsigned)gT, 256, GEMM2_SMEM, s0>>>(aggTh, h1t, wt2st, bl2_st, wctT, ut, N_TAXON);

    agg256_kernel<<<wS, 256, 0, s2>>>(h1t, rowS, adjS, aggSh, N_SOTU);
    gemm_l2p<<<(unsigned)gS, 256, GEMM2_SMEM, s2>>>(aggSh, h1s, wt2ts, bl2_ts, wcsT, us, N_SOTU);

    // ---- join, decode on s0 ----
    cudaEventRecord(ev[5], s2);
    cudaStreamWaitEvent(s0, ev[5], 0);

    decode_kernel<<<(NEL * 32 + 255) / 256, 256, 0, s0>>>(
        us, ut, lsrc, ldst,
        (const float4*)bdc, (const float4*)Wd2, bd2, out, NEL);
}

// round 14
// speedup vs baseline: 1.0273x; 1.0076x over previous
#include <cuda_runtime.h>
#include <cuda_fp16.h>
#include <cstdint>

#define N_SOTU  100000
#define N_TAXON 20000
#define NE      800000
#define NEL     200000
#define DS      256
#define DT      128
#define HID     256

#define WROW 264   // halves per weight row (256 data + 8 pad), k-major

#define NBA ((N_TAXON + 1023) / 1024)   // 20
#define NBB ((N_SOTU + 1023) / 1024)    // 98
#define NBT (NBA + NBB)                 // 118

// ---------------- scratch (device globals; no allocation) ----------------
__device__ __align__(128) __half g_aggTh[(size_t)N_TAXON*HID];
__device__ __align__(128) __half g_aggSh[(size_t)N_SOTU*HID];
__device__ __align__(128) __half g_h1t[(size_t)N_TAXON*HID];
__device__ __align__(128) __half g_h1s[(size_t)N_SOTU*HID];
__device__ __align__(128) __half g_us[(size_t)N_SOTU*HID];
__device__ __align__(128) __half g_ut[(size_t)N_TAXON*HID];
__device__ __align__(128) __half g_xr_s[(size_t)N_SOTU*DS];
__device__ __align__(128) __half g_xr_t[(size_t)N_TAXON*DT];
__device__ __align__(128) __half g_wt1_st[384*WROW];
__device__ __align__(128) __half g_wt1_ts[384*WROW];
__device__ __align__(128) __half g_wt2_st[512*WROW];
__device__ __align__(128) __half g_wt2_ts[512*WROW];
__device__ __align__(128) __half g_wcsT[256*WROW];
__device__ __align__(128) __half g_wctT[256*WROW];
__device__ __align__(128) float  g_bdc[256];
// CSR
__device__ int g_rowT[N_TAXON + 1];
__device__ int g_rowS[N_SOTU + 1];
__device__ int g_curT[N_TAXON];
__device__ int g_curS[N_SOTU];
__device__ int g_adjT[NE];
__device__ int g_adjS[NE];
__device__ int g_bsums[NBT];

// ---------------- prep kernels ----------------
__global__ void tohalf_dual(const float4* inA, __half2* outA, long long nA4,
                            const float4* inB, __half2* outB, long long nB4) {
    long long i = blockIdx.x * (long long)blockDim.x + threadIdx.x;
    const float4* in; __half2* out; long long idx;
    if (i < nA4) { in = inA; out = outA; idx = i; }
    else if (i - nA4 < nB4) { in = inB; out = outB; idx = i - nA4; }
    else return;
    float4 v = in[idx];
    out[idx * 2 + 0] = __floats2half2_rn(v.x, v.y);
    out[idx * 2 + 1] = __floats2half2_rn(v.z, v.w);
}

__global__ void wt_all(const float* W1a, const float* W2a, __half* Oa,
                       const float* W1b, const float* W2b, __half* Ob,
                       const float* W1c, const float* W2c, __half* Oc,
                       const float* W1d, const float* W2d, __half* Od) {
    int b = blockIdx.x, h = threadIdx.x;
    const float* W1; const float* W2; __half* O; int K1, K2, k;
    if (b < 384)        { W1 = W1a; W2 = W2a; O = Oa; K1 = 256; K2 = 128; k = b; }
    else if (b < 768)   { W1 = W1b; W2 = W2b; O = Ob; K1 = 128; K2 = 256; k = b - 384; }
    else if (b < 1280)  { W1 = W1c; W2 = W2c; O = Oc; K1 = 256; K2 = 256; k = b - 768; }
    else                { W1 = W1d; W2 = W2d; O = Od; K1 = 256; K2 = 256; k = b - 1280; }
    float v = (k < K1) ? W1[h * K1 + k] : W2[h * K2 + (k - K1)];
    O[(size_t)k * WROW + h] = __float2half_rn(v);
}

// ---------------- CSR build ----------------
__global__ void zero_dual(int* a, int na, int* b, int nb) {
    int i = blockIdx.x * blockDim.x + threadIdx.x;
    if (i < na) a[i] = 0;
    if (i < nb) b[i] = 0;
}

// 2 edges per thread (NE even)
__global__ void hist_kernel(const int2* __restrict__ src2, const int2* __restrict__ dst2,
                            int* curS, int* curT, int E2) {
    int e = blockIdx.x * blockDim.x + threadIdx.x;
    if (e >= E2) return;
    int2 s = __ldg(src2 + e), d = __ldg(dst2 + e);
    atomicAdd(curT + d.x, 1);
    atomicAdd(curT + d.y, 1);
    atomicAdd(curS + s.x, 1);
    atomicAdd(curS + s.y, 1);
}

// ---- 3-phase grid-wide dual exclusive scan ----
// phase 1: per-block local exclusive scan (1024 elems/block); zero cnt; emit block sums
__global__ void __launch_bounds__(1024)
scan_local(int* cntA, int* rowA, int nA,
           int* cntB, int* rowB, int nB, int* bsums) {
    __shared__ int wsum[32];
    int b = blockIdx.x;
    int* cnt; int* row; int n; int base;
    if (b < NBA) { cnt = cntA; row = rowA; n = nA; base = b * 1024; }
    else         { cnt = cntB; row = rowB; n = nB; base = (b - NBA) * 1024; }
    int tid = threadIdx.x, lane = tid & 31, wid = tid >> 5;
    int idx = base + tid;
    int v = (idx < n) ? cnt[idx] : 0;
    int x = v;
#pragma unroll
    for (int o = 1; o < 32; o <<= 1) {
        int t = __shfl_up_sync(0xffffffffu, x, o);
        if (lane >= o) x += t;
    }
    if (lane == 31) wsum[wid] = x;
    __syncthreads();
    if (wid == 0) {
        int y = wsum[lane];
#pragma unroll
        for (int o = 1; o < 32; o <<= 1) {
            int t = __shfl_up_sync(0xffffffffu, y, o);
            if (lane >= o) y += t;
        }
        wsum[lane] = y;
    }
    __syncthreads();
    int incl = x + (wid ? wsum[wid - 1] : 0);
    if (idx < n) { row[idx] = incl - v; cnt[idx] = 0; }
    if (tid == 1023) bsums[b] = incl;
}

// phase 2: single block scans the 118 block sums (two segments) -> exclusive offsets + tails
__global__ void __launch_bounds__(128)
scan_partials(int* bsums, int* rowA, int nA, int* rowB, int nB) {
    __shared__ int sm[128];
    int tid = threadIdx.x;
    int v = (tid < NBT) ? bsums[tid] : 0;
    sm[tid] = v;
    __syncthreads();
#pragma unroll
    for (int o = 1; o < 128; o <<= 1) {
        int t = (tid >= o) ? sm[tid - o] : 0;
        __syncthreads();
        sm[tid] += t;
        __syncthreads();
    }
    // sm now inclusive over all 118
    int inclA = sm[NBA - 1];
    if (tid < NBT) {
        int excl = tid ? sm[tid - 1] : 0;
        bsums[tid] = (tid >= NBA) ? (excl - inclA) : excl;
    }
    if (tid == 0) rowA[nA] = inclA;
    if (tid == 1) rowB[nB] = sm[NBT - 1] - inclA;
}

// phase 3: add block offsets
__global__ void __launch_bounds__(1024)
scan_add(int* rowA, int nA, int* rowB, int nB, const int* __restrict__ bsums) {
    int b = blockIdx.x;
    int off = __ldg(bsums + b);
    int* row; int n; int base;
    if (b < NBA) { row = rowA; n = nA; base = b * 1024; }
    else         { row = rowB; n = nB; base = (b - NBA) * 1024; }
    int idx = base + threadIdx.x;
    if (idx < n && off) row[idx] += off;
}

// 2 edges per thread
__global__ void fill_kernel(const int2* __restrict__ src2, const int2* __restrict__ dst2,
                            const int* __restrict__ rowT, int* curT, int* adjT,
                            const int* __restrict__ rowS, int* curS, int* adjS, int E2) {
    int e = blockIdx.x * blockDim.x + threadIdx.x;
    if (e >= E2) return;
    int2 s = __ldg(src2 + e), d = __ldg(dst2 + e);
    adjT[__ldg(rowT + d.x) + atomicAdd(curT + d.x, 1)] = s.x;
    adjS[__ldg(rowS + s.x) + atomicAdd(curS + s.x, 1)] = d.x;
    adjT[__ldg(rowT + d.y) + atomicAdd(curT + d.y, 1)] = s.y;
    adjS[__ldg(rowS + s.y) + atomicAdd(curS + s.y, 1)] = d.y;
}

// ---------------- warp-per-node mean aggregation (unroll x8) ----------------
__global__ void agg256_kernel(const __half* __restrict__ feat,
                              const int* __restrict__ rowp,
                              const int* __restrict__ adj,
                              __half* __restrict__ out, int nNodes) {
    int gw = (blockIdx.x * blockDim.x + threadIdx.x) >> 5;
    int lane = threadIdx.x & 31;
    if (gw >= nNodes) return;
    int s = __ldg(rowp + gw), e = __ldg(rowp + gw + 1);
    float acc[8] = {0.f, 0.f, 0.f, 0.f, 0.f, 0.f, 0.f, 0.f};
    const size_t lo = (size_t)lane * 8;
    int i = s;
    for (; i + 8 <= e; i += 8) {
        int nn[8];
#pragma unroll
        for (int q = 0; q < 8; q++) nn[q] = __ldg(adj + i + q);
        uint4 u[8];
#pragma unroll
        for (int q = 0; q < 8; q++) u[q] = *(const uint4*)(feat + (size_t)nn[q] * 256 + lo);
#pragma unroll
        for (int q = 0; q < 8; q++) {
            const __half2* h = (const __half2*)&u[q];
#pragma unroll
            for (int j = 0; j < 4; j++) {
                float2 f = __half22float2(h[j]);
                acc[2 * j]     += f.x;
                acc[2 * j + 1] += f.y;
            }
        }
    }
    for (; i + 4 <= e; i += 4) {
        int nn[4];
#pragma unroll
        for (int q = 0; q < 4; q++) nn[q] = __ldg(adj + i + q);
        uint4 u[4];
#pragma unroll
        for (int q = 0; q < 4; q++) u[q] = *(const uint4*)(feat + (size_t)nn[q] * 256 + lo);
#pragma unroll
        for (int q = 0; q < 4; q++) {
            const __half2* h = (const __half2*)&u[q];
#pragma unroll
            for (int j = 0; j < 4; j++) {
                float2 f = __half22float2(h[j]);
                acc[2 * j]     += f.x;
                acc[2 * j + 1] += f.y;
            }
        }
    }
    for (; i < e; i++) {
        int n0 = __ldg(adj + i);
        uint4 u0 = *(const uint4*)(feat + (size_t)n0 * 256 + lo);
        const __half2* h0 = (const __half2*)&u0;
#pragma unroll
        for (int j = 0; j < 4; j++) {
            float2 f0 = __half22float2(h0[j]);
            acc[2 * j]     += f0.x;
            acc[2 * j + 1] += f0.y;
        }
    }
    float inv = 1.f / fmaxf((float)(e - s), 1.f);
    __half2 o[4];
#pragma unroll
    for (int j = 0; j < 4; j++)
        o[j] = __floats2half2_rn(acc[2 * j] * inv, acc[2 * j + 1] * inv);
    *(uint4*)(out + (size_t)gw * 256 + lo) = *(uint4*)o;
}

__global__ void agg128_kernel(const __half* __restrict__ feat,
                              const int* __restrict__ rowp,
                              const int* __restrict__ adj,
                              __half* __restrict__ out, int nNodes) {
    int gw = (blockIdx.x * blockDim.x + threadIdx.x) >> 5;
    int lane = threadIdx.x & 31;
    if (gw >= nNodes) return;
    int s = __ldg(rowp + gw), e = __ldg(rowp + gw + 1);
    float acc[4] = {0.f, 0.f, 0.f, 0.f};
    const size_t lo = (size_t)lane * 4;
    int i = s;
    for (; i + 8 <= e; i += 8) {
        int nn[8];
#pragma unroll
        for (int q = 0; q < 8; q++) nn[q] = __ldg(adj + i + q);
        uint2 u[8];
#pragma unroll
        for (int q = 0; q < 8; q++) u[q] = *(const uint2*)(feat + (size_t)nn[q] * 128 + lo);
#pragma unroll
        for (int q = 0; q < 8; q++) {
            const __half2* h = (const __half2*)&u[q];
#pragma unroll
            for (int j = 0; j < 2; j++) {
                float2 f = __half22float2(h[j]);
                acc[2 * j]     += f.x;
                acc[2 * j + 1] += f.y;
            }
        }
    }
    for (; i + 4 <= e; i += 4) {
        int nn[4];
#pragma unroll
        for (int q = 0; q < 4; q++) nn[q] = __ldg(adj + i + q);
        uint2 u[4];
#pragma unroll
        for (int q = 0; q < 4; q++) u[q] = *(const uint2*)(feat + (size_t)nn[q] * 128 + lo);
#pragma unroll
        for (int q = 0; q < 4; q++) {
            const __half2* h = (const __half2*)&u[q];
#pragma unroll
            for (int j = 0; j < 2; j++) {
                float2 f = __half22float2(h[j]);
                acc[2 * j]     += f.x;
                acc[2 * j + 1] += f.y;
            }
        }
    }
    for (; i < e; i++) {
        int n0 = __ldg(adj + i);
        uint2 u0 = *(const uint2*)(feat + (size_t)n0 * 128 + lo);
        const __half2* h0 = (const __half2*)&u0;
#pragma unroll
        for (int j = 0; j < 2; j++) {
            float2 f0 = __half22float2(h0[j]);
            acc[2 * j]     += f0.x;
            acc[2 * j + 1] += f0.y;
        }
    }
    float inv = 1.f / fmaxf((float)(e - s), 1.f);
    __half2 o[2];
#pragma unroll
    for (int j = 0; j < 2; j++)
        o[j] = __floats2half2_rn(acc[2 * j] * inv, acc[2 * j + 1] * inv);
    *(uint2*)(out + (size_t)gw * 128 + lo) = *(uint2*)o;
}

// ---------------- fp16 HMMA GEMM machinery (ldmatrix fragments, R9 config) ----------------
#define A_ROW_B 80
#define B_ROW_B 528
#define A_STAGE_B (128*A_ROW_B)
#define B_STAGE_B (32*B_ROW_B)
#define STAGE_B   (A_STAGE_B + B_STAGE_B)
#define GEMM1_SMEM (4*STAGE_B)
#define H2_ROW_B 528
#define H2_TILE_B (128*H2_ROW_B)
#define GEMM2_SMEM (4*STAGE_B + H2_TILE_B)

__device__ __forceinline__ void mma_f16(float* d, const uint32_t* a, const uint32_t* b) {
    asm volatile(
        "mma.sync.aligned.m16n8k16.row.col.f32.f16.f16.f32 "
        "{%0,%1,%2,%3}, {%4,%5,%6,%7}, {%8,%9}, {%0,%1,%2,%3};"
        : "+f"(d[0]), "+f"(d[1]), "+f"(d[2]), "+f"(d[3])
        : "r"(a[0]), "r"(a[1]), "r"(a[2]), "r"(a[3]), "r"(b[0]), "r"(b[1]));
}
__device__ __forceinline__ void ldm_x4(uint32_t* r, uint32_t addr) {
    asm volatile("ldmatrix.sync.aligned.m8n8.x4.shared.b16 {%0,%1,%2,%3}, [%4];"
        : "=r"(r[0]), "=r"(r[1]), "=r"(r[2]), "=r"(r[3]) : "r"(addr));
}
__device__ __forceinline__ void ldm_x4t(uint32_t* r, uint32_t addr) {
    asm volatile("ldmatrix.sync.aligned.m8n8.x4.trans.shared.b16 {%0,%1,%2,%3}, [%4];"
        : "=r"(r[0]), "=r"(r[1]), "=r"(r[2]), "=r"(r[3]) : "r"(addr));
}

__device__ __forceinline__ void issue_ab(uint32_t sbase, int c, int k0, int K1,
                                         const __half* A1, const __half* A2, int K2,
                                         const __half* WTk, int bm, int Nrows, int tid) {
    int slot = c & 3;
    uint32_t aoff = sbase + slot * STAGE_B;
    uint32_t boff = aoff + A_STAGE_B;
    bool inA1 = (k0 < K1);
#pragma unroll
    for (int i = 0; i < 2; i++) {
        int idx = tid + i * 256;
        int row = idx >> 2, seg8 = (idx & 3) * 8;
        int grow = bm + row;
        bool ok = grow < Nrows;
        int gr = ok ? grow : 0;
        const __half* src = inA1 ? A1 + (size_t)gr * K1 + k0 + seg8
                                 : A2 + (size_t)gr * K2 + (k0 - K1) + seg8;
        uint32_t dst = aoff + (uint32_t)(row * A_ROW_B + seg8 * 2);
        int sz = ok ? 16 : 0;
        asm volatile("cp.async.cg.shared.global [%0], [%1], 16, %2;"
                     :: "r"(dst), "l"(src), "r"(sz));
    }
#pragma unroll
    for (int i = 0; i < 4; i++) {
        int idx = tid + i * 256;
        int kr = idx >> 5, seg = idx & 31;
        const __half* src = WTk + (size_t)(k0 + kr) * WROW + seg * 8;
        uint32_t dst = boff + (uint32_t)(kr * B_ROW_B + seg * 16);
        asm volatile("cp.async.cg.shared.global [%0], [%1], 16;"
                     :: "r"(dst), "l"(src));
    }
    asm volatile("cp.async.commit_group;");
}

__device__ __forceinline__ void issue_b(uint32_t sbase, int c, const __half* P, int tid) {
    int slot = c & 3;
    uint32_t boff = sbase + slot * STAGE_B + A_STAGE_B;
    int k0 = c << 5;
#pragma unroll
    for (int i = 0; i < 4; i++) {
        int idx = tid + i * 256;
        int kr = idx >> 5, seg = idx & 31;
        const __half* src = P + (size_t)(k0 + kr) * WROW + seg * 8;
        uint32_t dst = boff + (uint32_t)(kr * B_ROW_B + seg * 16);
        asm volatile("cp.async.cg.shared.global [%0], [%1], 16;"
                     :: "r"(dst), "l"(src));
    }
    asm volatile("cp.async.commit_group;");
}

__device__ __forceinline__ void mma_chunk(uint32_t aBase, uint32_t bBase, float acc[4][8][4]) {
#pragma unroll
    for (int s = 0; s < 2; s++) {
        uint32_t af[4][4], bf[4][4];
#pragma unroll
        for (int mt = 0; mt < 4; mt++)
            ldm_x4(af[mt], aBase + mt * (16 * A_ROW_B) + s * 32);
#pragma unroll
        for (int p = 0; p < 4; p++)
            ldm_x4t(bf[p], bBase + s * (16 * B_ROW_B) + p * 32);
#pragma unroll
        for (int mt = 0; mt < 4; mt++)
#pragma unroll
            for (int p = 0; p < 4; p++) {
                mma_f16(acc[mt][2 * p],     af[mt], &bf[p][0]);
                mma_f16(acc[mt][2 * p + 1], af[mt], &bf[p][2]);
            }
    }
}

// ---------------- layer-1 GEMM: relu epilogue (256 threads) ----------------
__global__ void __launch_bounds__(256)
gemm_sage(const __half* A1, int K1, const __half* A2, int K2,
          const __half* W, const float* bias, __half* C, int Nrows) {
    extern __shared__ char sm[];
    const int tid = threadIdx.x;
    const int wid = tid >> 5, lane = tid & 31;
    const int warpM = wid >> 2, warpN = wid & 3;
    const int lrow = lane >> 2, lcol = lane & 3;
    const int bm = blockIdx.x * 128;
    const int nch = (K1 + K2) >> 5;

    uint32_t sbase = (uint32_t)__cvta_generic_to_shared(sm);
    const uint32_t aLane = (uint32_t)((warpM * 64 + (lane & 15)) * A_ROW_B + ((lane & 16) ? 16 : 0));
    const uint32_t bLane = (uint32_t)((lane & 15) * B_ROW_B + (warpN * 64 + ((lane & 16) ? 8 : 0)) * 2);

    float2 bv[8];
#pragma unroll
    for (int nt = 0; nt < 8; nt++) {
        int col = warpN * 64 + nt * 8 + 2 * lcol;
        bv[nt].x = __ldg(bias + col); bv[nt].y = __ldg(bias + col + 1);
    }

    float acc[4][8][4];
#pragma unroll
    for (int i = 0; i < 4; i++)
#pragma unroll
        for (int j = 0; j < 8; j++)
#pragma unroll
            for (int q = 0; q < 4; q++) acc[i][j][q] = 0.f;

    issue_ab(sbase, 0, 0, K1, A1, A2, K2, W, bm, Nrows, tid);
    issue_ab(sbase, 1, 32, K1, A1, A2, K2, W, bm, Nrows, tid);
    issue_ab(sbase, 2, 64, K1, A1, A2, K2, W, bm, Nrows, tid);

    for (int c = 0; c < nch; c++) {
        asm volatile("cp.async.wait_group 2;");
        __syncthreads();
        if (c + 3 < nch) issue_ab(sbase, c + 3, (c + 3) << 5, K1, A1, A2, K2, W, bm, Nrows, tid);
        else asm volatile("cp.async.commit_group;");
        int slot = c & 3;
        mma_chunk(sbase + slot * STAGE_B + aLane,
                  sbase + slot * STAGE_B + A_STAGE_B + bLane, acc);
    }

#pragma unroll
    for (int mt = 0; mt < 4; mt++) {
        const int r0 = bm + warpM * 64 + mt * 16 + lrow;
#pragma unroll
        for (int half = 0; half < 2; half++) {
            const int row = r0 + half * 8;
            if (row >= Nrows) continue;
#pragma unroll
            for (int nt = 0; nt < 8; nt++) {
                const int col = warpN * 64 + nt * 8 + 2 * lcol;
                float vx = fmaxf(acc[mt][nt][half * 2 + 0] + bv[nt].x, 0.f);
                float vy = fmaxf(acc[mt][nt][half * 2 + 1] + bv[nt].y, 0.f);
                *(__half2*)(C + (size_t)row * 256 + col) = __floats2half2_rn(vx, vy);
            }
        }
    }
}

// ---------------- layer-2 GEMM + fused projection (256 threads) ----------------
__global__ void __launch_bounds__(256)
gemm_l2p(const __half* A1, const __half* A2, const __half* W, const float* bias,
         const __half* P, __half* U, int Nrows) {
    extern __shared__ char sm[];
    const int tid = threadIdx.x;
    const int wid = tid >> 5, lane = tid & 31;
    const int warpM = wid >> 2, warpN = wid & 3;
    const int lrow = lane >> 2, lcol = lane & 3;
    const int bm = blockIdx.x * 128;
    const int K1 = HID;
    const int nch = 16;

    uint32_t sbase = (uint32_t)__cvta_generic_to_shared(sm);
    uint32_t* H2 = (uint32_t*)(sm + 4 * STAGE_B);
    const uint32_t h2base = sbase + 4 * STAGE_B;
    const uint32_t aLane = (uint32_t)((warpM * 64 + (lane & 15)) * A_ROW_B + ((lane & 16) ? 16 : 0));
    const uint32_t bLane = (uint32_t)((lane & 15) * B_ROW_B + (warpN * 64 + ((lane & 16) ? 8 : 0)) * 2);
    const uint32_t h2Lane = h2base + (uint32_t)((warpM * 64 + (lane & 15)) * H2_ROW_B + ((lane & 16) ? 16 : 0));

    float2 bv[8];
#pragma unroll
    for (int nt = 0; nt < 8; nt++) {
        int col = warpN * 64 + nt * 8 + 2 * lcol;
        bv[nt].x = __ldg(bias + col); bv[nt].y = __ldg(bias + col + 1);
    }

    float acc[4][8][4];
#pragma unroll
    for (int i = 0; i < 4; i++)
#pragma unroll
        for (int j = 0; j < 8; j++)
#pragma unroll
            for (int q = 0; q < 4; q++) acc[i][j][q] = 0.f;

    issue_ab(sbase, 0, 0, K1, A1, A2, HID, W, bm, Nrows, tid);
    issue_ab(sbase, 1, 32, K1, A1, A2, HID, W, bm, Nrows, tid);
    issue_ab(sbase, 2, 64, K1, A1, A2, HID, W, bm, Nrows, tid);

    for (int c = 0; c < nch; c++) {
        asm volatile("cp.async.wait_group 2;");
        __syncthreads();
        if (c + 3 < nch) issue_ab(sbase, c + 3, (c + 3) << 5, K1, A1, A2, HID, W, bm, Nrows, tid);
        else asm volatile("cp.async.commit_group;");
        int slot = c & 3;
        mma_chunk(sbase + slot * STAGE_B + aLane,
                  sbase + slot * STAGE_B + A_STAGE_B + bLane, acc);
    }

    // store h2 tile (bias+relu, half) into smem; re-zero acc
#pragma unroll
    for (int mt = 0; mt < 4; mt++) {
#pragma unroll
        for (int half = 0; half < 2; half++) {
            const int row = warpM * 64 + mt * 16 + lrow + half * 8;
#pragma unroll
            for (int nt = 0; nt < 8; nt++) {
                const int col2 = warpN * 32 + nt * 4 + lcol;
                float vx = fmaxf(acc[mt][nt][half * 2 + 0] + bv[nt].x, 0.f);
                float vy = fmaxf(acc[mt][nt][half * 2 + 1] + bv[nt].y, 0.f);
                __half2 hv = __floats2half2_rn(vx, vy);
                H2[row * (H2_ROW_B / 4) + col2] = *(uint32_t*)&hv;
            }
        }
    }
#pragma unroll
    for (int i = 0; i < 4; i++)
#pragma unroll
        for (int j = 0; j < 8; j++)
#pragma unroll
            for (int q = 0; q < 4; q++) acc[i][j][q] = 0.f;
    __syncthreads();

    // projection loop: u = h2 @ P
    issue_b(sbase, 0, P, tid);
    issue_b(sbase, 1, P, tid);
    issue_b(sbase, 2, P, tid);

    for (int c = 0; c < 8; c++) {
        asm volatile("cp.async.wait_group 2;");
        __syncthreads();
        if (c + 3 < 8) issue_b(sbase, c + 3, P, tid);
        else asm volatile("cp.async.commit_group;");
        int slot = c & 3;
        uint32_t bB = sbase + slot * STAGE_B + A_STAGE_B + bLane;
#pragma unroll
        for (int s = 0; s < 2; s++) {
            uint32_t af[4][4], bf[4][4];
#pragma unroll
            for (int mt = 0; mt < 4; mt++)
                ldm_x4(af[mt], h2Lane + mt * (16 * H2_ROW_B) + c * 64 + s * 32);
#pragma unroll
            for (int p = 0; p < 4; p++)
                ldm_x4t(bf[p], bB + s * (16 * B_ROW_B) + p * 32);
#pragma unroll
            for (int mt = 0; mt < 4; mt++)
#pragma unroll
                for (int p = 0; p < 4; p++) {
                    mma_f16(acc[mt][2 * p],     af[mt], &bf[p][0]);
                    mma_f16(acc[mt][2 * p + 1], af[mt], &bf[p][2]);
                }
        }
    }

#pragma unroll
    for (int mt = 0; mt < 4; mt++) {
        const int r0 = bm + warpM * 64 + mt * 16 + lrow;
#pragma unroll
        for (int half = 0; half < 2; half++) {
            const int row = r0 + half * 8;
            if (row >= Nrows) continue;
#pragma unroll
            for (int nt = 0; nt < 8; nt++) {
                const int col = warpN * 64 + nt * 8 + 2 * lcol;
                *(__half2*)(U + (size_t)row * 256 + col) =
                    __floats2half2_rn(acc[mt][nt][half * 2 + 0], acc[mt][nt][half * 2 + 1]);
            }
        }
    }
}

// ---------------- weight composition (k-major half output) ----------------
__global__ void compose_kernel(const float* __restrict__ Wd1,
                               const float* __restrict__ Wlin_s,
                               const float* __restrict__ Wlin_t,
                               const float* __restrict__ blin_s,
                               const float* __restrict__ blin_t,
                               const float* __restrict__ bd1,
                               __half* WcsT, __half* WctT, float* bdc) {
    int i = blockIdx.x;
    int m = threadIdx.x;
    float ss = 0.f, st = 0.f;
    for (int k = 0; k < HID; k++) {
        float wl = Wd1[i * 2 * HID + k];
        float wr = Wd1[i * 2 * HID + HID + k];
        ss += wl * Wlin_s[k * HID + m];
        st += wr * Wlin_t[k * HID + m];
    }
    WcsT[(size_t)m * WROW + i] = __float2half_rn(ss);
    WctT[(size_t)m * WROW + i] = __float2half_rn(st);
    if (m == 0) {
        float b = bd1[i];
        for (int k = 0; k < HID; k++) {
            b += Wd1[i * 2 * HID + k] * blin_s[k];
            b += Wd1[i * 2 * HID + HID + k] * blin_t[k];
        }
        bdc[i] = b;
    }
}

// ---------------- decoder: 2 edges per warp (16 lanes each) ----------------
__global__ void decode_kernel(const __half* __restrict__ us, const __half* __restrict__ ut,
                              const int* __restrict__ ls, const int* __restrict__ ld,
                              const float* __restrict__ bdc, const float* __restrict__ wd2,
                              const float* __restrict__ bd2,
                              float* __restrict__ out, int EL2) {
    int g = blockIdx.x * blockDim.x + threadIdx.x;
    int w = g >> 5, lane = g & 31;
    if (w >= EL2) return;
    int half = lane >> 4, l16 = lane & 15;
    int edge = w * 2 + half;
    const uint4* a = (const uint4*)(us + (size_t)__ldg(ls + edge) * HID) + l16 * 2;
    const uint4* b = (const uint4*)(ut + (size_t)__ldg(ld + edge) * HID) + l16 * 2;
    uint4 ua0 = a[0], ua1 = a[1];
    uint4 ub0 = b[0], ub1 = b[1];
    float cb[16], wb[16];
#pragma unroll
    for (int j = 0; j < 4; j++) {
        *(float4*)&cb[j * 4] = __ldg((const float4*)bdc + l16 * 4 + j);
        *(float4*)&wb[j * 4] = __ldg((const float4*)wd2 + l16 * 4 + j);
    }
    const __half2* ha0 = (const __half2*)&ua0;
    const __half2* ha1 = (const __half2*)&ua1;
    const __half2* hb0 = (const __half2*)&ub0;
    const __half2* hb1 = (const __half2*)&ub1;
    float sum = 0.f;
#pragma unroll
    for (int k = 0; k < 4; k++) {
        float2 fa = __half22float2(ha0[k]), fb = __half22float2(hb0[k]);
        sum += fmaxf(fa.x + fb.x + cb[2 * k], 0.f) * wb[2 * k]
             + fmaxf(fa.y + fb.y + cb[2 * k + 1], 0.f) * wb[2 * k + 1];
    }
#pragma unroll
    for (int k = 0; k < 4; k++) {
        float2 fa = __half22float2(ha1[k]), fb = __half22float2(hb1[k]);
        sum += fmaxf(fa.x + fb.x + cb[8 + 2 * k], 0.f) * wb[8 + 2 * k]
             + fmaxf(fa.y + fb.y + cb[8 + 2 * k + 1], 0.f) * wb[8 + 2 * k + 1];
    }
#pragma unroll
    for (int o = 8; o; o >>= 1) sum += __shfl_xor_sync(0xffffffffu, sum, o);
    if (l16 == 0) out[edge] = sum + bd2[0];
}

// ---------------- launcher (R9 schedule) ----------------
extern "C" void kernel_launch(void* const* d_in, const int* in_sizes, int n_in,
                              void* d_out, int out_size) {
    const float* x_sotu  = (const float*)d_in[0];
    const float* x_taxon = (const float*)d_in[1];
    const int*   esrc    = (const int*)d_in[2];
    const int*   edst    = (const int*)d_in[3];
    const int*   lsrc    = (const int*)d_in[4];
    const int*   ldst    = (const int*)d_in[5];
    const float* Wl1_st  = (const float*)d_in[6];
    const float* bl1_st  = (const float*)d_in[7];
    const float* Wr1_st  = (const float*)d_in[8];
    const float* Wl1_ts  = (const float*)d_in[9];
    const float* bl1_ts  = (const float*)d_in[10];
    const float* Wr1_ts  = (const float*)d_in[11];
    const float* Wl2_st  = (const float*)d_in[12];
    const float* bl2_st  = (const float*)d_in[13];
    const float* Wr2_st  = (const float*)d_in[14];
    const float* Wl2_ts  = (const float*)d_in[15];
    const float* bl2_ts  = (const float*)d_in[16];
    const float* Wr2_ts  = (const float*)d_in[17];
    const float* Wlin_s  = (const float*)d_in[18];
    const float* blin_s  = (const float*)d_in[19];
    const float* Wlin_t  = (const float*)d_in[20];
    const float* blin_t  = (const float*)d_in[21];
    const float* Wd1     = (const float*)d_in[22];
    const float* bd1     = (const float*)d_in[23];
    const float* Wd2     = (const float*)d_in[24];
    const float* bd2     = (const float*)d_in[25];
    float* out = (float*)d_out;

    float *bdc;
    __half *aggTh, *aggSh, *h1t, *h1s, *us, *ut;
    __half *xrs, *xrt, *wt1st, *wt1ts, *wt2st, *wt2ts, *wcsT, *wctT;
    int *rowT, *rowS, *curT, *curS, *adjT, *adjS, *bsums;
    cudaGetSymbolAddress((void**)&aggTh, g_aggTh);
    cudaGetSymbolAddress((void**)&aggSh, g_aggSh);
    cudaGetSymbolAddress((void**)&h1t, g_h1t);
    cudaGetSymbolAddress((void**)&h1s, g_h1s);
    cudaGetSymbolAddress((void**)&us,  g_us);
    cudaGetSymbolAddress((void**)&ut,  g_ut);
    cudaGetSymbolAddress((void**)&xrs, g_xr_s);
    cudaGetSymbolAddress((void**)&xrt, g_xr_t);
    cudaGetSymbolAddress((void**)&wt1st, g_wt1_st);
    cudaGetSymbolAddress((void**)&wt1ts, g_wt1_ts);
    cudaGetSymbolAddress((void**)&wt2st, g_wt2_st);
    cudaGetSymbolAddress((void**)&wt2ts, g_wt2_ts);
    cudaGetSymbolAddress((void**)&wcsT, g_wcsT);
    cudaGetSymbolAddress((void**)&wctT, g_wctT);
    cudaGetSymbolAddress((void**)&bdc, g_bdc);
    cudaGetSymbolAddress((void**)&rowT, g_rowT);
    cudaGetSymbolAddress((void**)&rowS, g_rowS);
    cudaGetSymbolAddress((void**)&curT, g_curT);
    cudaGetSymbolAddress((void**)&curS, g_curS);
    cudaGetSymbolAddress((void**)&adjT, g_adjT);
    cudaGetSymbolAddress((void**)&adjS, g_adjS);
    cudaGetSymbolAddress((void**)&bsums, g_bsums);

    static cudaStream_t s2 = nullptr;
    static cudaEvent_t ev[8];
    static int inited = 0;
    if (!inited) {
        cudaFuncSetAttribute(gemm_sage, cudaFuncAttributeMaxDynamicSharedMemorySize, GEMM1_SMEM);
        cudaFuncSetAttribute(gemm_l2p, cudaFuncAttributeMaxDynamicSharedMemorySize, GEMM2_SMEM);
        cudaStreamCreateWithFlags(&s2, cudaStreamNonBlocking);
        for (int i = 0; i < 8; i++) cudaEventCreateWithFlags(&ev[i], cudaEventDisableTiming);
        inited = 1;
    }
    cudaStream_t s0 = 0;

    const int gT = (N_TAXON + 127) / 128;   // 157
    const int gS = (N_SOTU + 127) / 128;    // 782
    const unsigned wT = (N_TAXON * 32 + 255) / 256;
    const unsigned wS = (N_SOTU * 32 + 255) / 256;

    // ---- fork 1: prep on s0 || CSR on s2 ----
    cudaEventRecord(ev[0], s0);
    cudaStreamWaitEvent(s2, ev[0], 0);

    long long nxs4 = (long long)N_SOTU * DS / 4, nxt4 = (long long)N_TAXON * DT / 4;
    tohalf_dual<<<(unsigned)((nxs4 + nxt4 + 255) / 256), 256, 0, s0>>>(
        (const float4*)x_sotu, (__half2*)xrs, nxs4,
        (const float4*)x_taxon, (__half2*)xrt, nxt4);
    wt_all<<<1792, 256, 0, s0>>>(Wl1_st, Wr1_st, wt1st,
                                 Wl1_ts, Wr1_ts, wt1ts,
                                 Wl2_st, Wr2_st, wt2st,
                                 Wl2_ts, Wr2_ts, wt2ts);
    compose_kernel<<<HID, HID, 0, s0>>>(Wd1, Wlin_s, Wlin_t, blin_s, blin_t, bd1, wcsT, wctT, bdc);

    zero_dual<<<(N_SOTU + 255) / 256, 256, 0, s2>>>(curT, N_TAXON, curS, N_SOTU);
    hist_kernel<<<(NE / 2 + 255) / 256, 256, 0, s2>>>(
        (const int2*)esrc, (const int2*)edst, curS, curT, NE / 2);
    scan_local<<<NBT, 1024, 0, s2>>>(curT, rowT, N_TAXON, curS, rowS, N_SOTU, bsums);
    scan_partials<<<1, 128, 0, s2>>>(bsums, rowT, N_TAXON, rowS, N_SOTU);
    scan_add<<<NBT, 1024, 0, s2>>>(rowT, N_TAXON, rowS, N_SOTU, bsums);
    fill_kernel<<<(NE / 2 + 255) / 256, 256, 0, s2>>>(
        (const int2*)esrc, (const int2*)edst, rowT, curT, adjT, rowS, curS, adjS, NE / 2);

    // ---- join, then fork 2: layer-1 taxon chain on s0 || sotu chain on s2 ----
    cudaEventRecord(ev[1], s2);
    cudaStreamWaitEvent(s0, ev[1], 0);
    cudaEventRecord(ev[2], s0);
    cudaStreamWaitEvent(s2, ev[2], 0);

    agg256_kernel<<<wT, 256, 0, s0>>>(xrs, rowT, adjT, aggTh, N_TAXON);
    gemm_sage<<<(unsigned)gT, 256, GEMM1_SMEM, s0>>>(aggTh, DS, xrt, DT, wt1st, bl1_st, h1t, N_TAXON);

    agg128_kernel<<<wS, 256, 0, s2>>>(xrt, rowS, adjS, aggSh, N_SOTU);
    gemm_sage<<<(unsigned)gS, 256, GEMM1_SMEM, s2>>>(aggSh, DT, xrs, DS, wt1ts, bl1_ts, h1s, N_SOTU);

    // ---- join (layer 2 needs both h1t and h1s), fork 3 ----
    cudaEventRecord(ev[3], s2);
    cudaStreamWaitEvent(s0, ev[3], 0);
    cudaEventRecord(ev[4], s0);
    cudaStreamWaitEvent(s2, ev[4], 0);

    agg256_kernel<<<wT, 256, 0, s0>>>(h1s, rowT, adjT, aggTh, N_TAXON);
    gemm_l2p<<<(unsigned)gT, 256, GEMM2_SMEM, s0>>>(aggTh, h1t, wt2st, bl2_st, wctT, ut, N_TAXON);

    agg256_kernel<<<wS, 256, 0, s2>>>(h1t, rowS, adjS, aggSh, N_SOTU);
    gemm_l2p<<<(unsigned)gS, 256, GEMM2_SMEM, s2>>>(aggSh, h1s, wt2ts, bl2_ts, wcsT, us, N_SOTU);

    // ---- join, decode on s0 ----
    cudaEventRecord(ev[5], s2);
    cudaStreamWaitEvent(s0, ev[5], 0);

    decode_kernel<<<(NEL / 2 * 32 + 255) / 256, 256, 0, s0>>>(
        us, ut, lsrc, ldst, bdc, Wd2, bd2, out, NEL / 2);
}

// round 15
// speedup vs baseline: 1.0592x; 1.0310x over previous
#include <cuda_runtime.h>
#include <cuda_fp16.h>
#include <cstdint>

#define N_SOTU  100000
#define N_TAXON 20000
#define NE      800000
#define NEL     200000
#define DS      256
#define DT      128
#define HID     256

#define WROW 264   // halves per weight row (256 data + 8 pad), k-major

#define NBA ((N_TAXON + 1023) / 1024)   // 20
#define NBB ((N_SOTU + 1023) / 1024)    // 98
#define NBT (NBA + NBB)                 // 118

// ---------------- scratch (device globals; no allocation) ----------------
__device__ __align__(128) __half g_aggTh[(size_t)N_TAXON*HID];
__device__ __align__(128) __half g_aggSh[(size_t)N_SOTU*HID];
__device__ __align__(128) __half g_h1t[(size_t)N_TAXON*HID];
__device__ __align__(128) __half g_h1s[(size_t)N_SOTU*HID];
__device__ __align__(128) __half g_p1t[(size_t)N_TAXON*HID];
__device__ __align__(128) __half g_us[(size_t)N_SOTU*HID];
__device__ __align__(128) __half g_ut[(size_t)N_TAXON*HID];
__device__ __align__(128) __half g_xr_s[(size_t)N_SOTU*DS];
__device__ __align__(128) __half g_xr_t[(size_t)N_TAXON*DT];
__device__ __align__(128) __half g_wt1_st[384*WROW];
__device__ __align__(128) __half g_wt1_ts[384*WROW];
__device__ __align__(128) __half g_wt2_st[512*WROW];
__device__ __align__(128) __half g_wt2_ts[512*WROW];
__device__ __align__(128) __half g_wcsT[256*WROW];
__device__ __align__(128) __half g_wctT[256*WROW];
__device__ __align__(128) float  g_bdc[256];
__device__ __align__(128) float  g_zero[256];   // static zero bias
// CSR
__device__ int g_rowT[N_TAXON + 1];
__device__ int g_rowS[N_SOTU + 1];
__device__ int g_curT[N_TAXON];
__device__ int g_curS[N_SOTU];
__device__ int g_adjT[NE];
__device__ int g_adjS[NE];
__device__ int g_bsums[NBT];

// ---------------- prep kernels ----------------
__global__ void tohalf_dual(const float4* inA, __half2* outA, long long nA4,
                            const float4* inB, __half2* outB, long long nB4) {
    long long i = blockIdx.x * (long long)blockDim.x + threadIdx.x;
    const float4* in; __half2* out; long long idx;
    if (i < nA4) { in = inA; out = outA; idx = i; }
    else if (i - nA4 < nB4) { in = inB; out = outB; idx = i - nA4; }
    else return;
    float4 v = in[idx];
    out[idx * 2 + 0] = __floats2half2_rn(v.x, v.y);
    out[idx * 2 + 1] = __floats2half2_rn(v.z, v.w);
}

__global__ void wt_all(const float* W1a, const float* W2a, __half* Oa,
                       const float* W1b, const float* W2b, __half* Ob,
                       const float* W1c, const float* W2c, __half* Oc,
                       const float* W1d, const float* W2d, __half* Od) {
    int b = blockIdx.x, h = threadIdx.x;
    const float* W1; const float* W2; __half* O; int K1, K2, k;
    if (b < 384)        { W1 = W1a; W2 = W2a; O = Oa; K1 = 256; K2 = 128; k = b; }
    else if (b < 768)   { W1 = W1b; W2 = W2b; O = Ob; K1 = 128; K2 = 256; k = b - 384; }
    else if (b < 1280)  { W1 = W1c; W2 = W2c; O = Oc; K1 = 256; K2 = 256; k = b - 768; }
    else                { W1 = W1d; W2 = W2d; O = Od; K1 = 256; K2 = 256; k = b - 1280; }
    float v = (k < K1) ? W1[h * K1 + k] : W2[h * K2 + (k - K1)];
    O[(size_t)k * WROW + h] = __float2half_rn(v);
}

// ---------------- CSR build ----------------
__global__ void zero_dual(int* a, int na, int* b, int nb) {
    int i = blockIdx.x * blockDim.x + threadIdx.x;
    if (i < na) a[i] = 0;
    if (i < nb) b[i] = 0;
}

__global__ void hist_kernel(const int2* __restrict__ src2, const int2* __restrict__ dst2,
                            int* curS, int* curT, int E2) {
    int e = blockIdx.x * blockDim.x + threadIdx.x;
    if (e >= E2) return;
    int2 s = __ldg(src2 + e), d = __ldg(dst2 + e);
    atomicAdd(curT + d.x, 1);
    atomicAdd(curT + d.y, 1);
    atomicAdd(curS + s.x, 1);
    atomicAdd(curS + s.y, 1);
}

__global__ void __launch_bounds__(1024)
scan_local(int* cntA, int* rowA, int nA,
           int* cntB, int* rowB, int nB, int* bsums) {
    __shared__ int wsum[32];
    int b = blockIdx.x;
    int* cnt; int* row; int n; int base;
    if (b < NBA) { cnt = cntA; row = rowA; n = nA; base = b * 1024; }
    else         { cnt = cntB; row = rowB; n = nB; base = (b - NBA) * 1024; }
    int tid = threadIdx.x, lane = tid & 31, wid = tid >> 5;
    int idx = base + tid;
    int v = (idx < n) ? cnt[idx] : 0;
    int x = v;
#pragma unroll
    for (int o = 1; o < 32; o <<= 1) {
        int t = __shfl_up_sync(0xffffffffu, x, o);
        if (lane >= o) x += t;
    }
    if (lane == 31) wsum[wid] = x;
    __syncthreads();
    if (wid == 0) {
        int y = wsum[lane];
#pragma unroll
        for (int o = 1; o < 32; o <<= 1) {
            int t = __shfl_up_sync(0xffffffffu, y, o);
            if (lane >= o) y += t;
        }
        wsum[lane] = y;
    }
    __syncthreads();
    int incl = x + (wid ? wsum[wid - 1] : 0);
    if (idx < n) { row[idx] = incl - v; cnt[idx] = 0; }
    if (tid == 1023) bsums[b] = incl;
}

__global__ void __launch_bounds__(128)
scan_partials(int* bsums, int* rowA, int nA, int* rowB, int nB) {
    __shared__ int sm[128];
    int tid = threadIdx.x;
    int v = (tid < NBT) ? bsums[tid] : 0;
    sm[tid] = v;
    __syncthreads();
#pragma unroll
    for (int o = 1; o < 128; o <<= 1) {
        int t = (tid >= o) ? sm[tid - o] : 0;
        __syncthreads();
        sm[tid] += t;
        __syncthreads();
    }
    int inclA = sm[NBA - 1];
    if (tid < NBT) {
        int excl = tid ? sm[tid - 1] : 0;
        bsums[tid] = (tid >= NBA) ? (excl - inclA) : excl;
    }
    if (tid == 0) rowA[nA] = inclA;
    if (tid == 1) rowB[nB] = sm[NBT - 1] - inclA;
}

__global__ void __launch_bounds__(1024)
scan_add(int* rowA, int nA, int* rowB, int nB, const int* __restrict__ bsums) {
    int b = blockIdx.x;
    int off = __ldg(bsums + b);
    int* row; int n; int base;
    if (b < NBA) { row = rowA; n = nA; base = b * 1024; }
    else         { row = rowB; n = nB; base = (b - NBA) * 1024; }
    int idx = base + threadIdx.x;
    if (idx < n && off) row[idx] += off;
}

__global__ void fill_kernel(const int2* __restrict__ src2, const int2* __restrict__ dst2,
                            const int* __restrict__ rowT, int* curT, int* adjT,
                            const int* __restrict__ rowS, int* curS, int* adjS, int E2) {
    int e = blockIdx.x * blockDim.x + threadIdx.x;
    if (e >= E2) return;
    int2 s = __ldg(src2 + e), d = __ldg(dst2 + e);
    adjT[__ldg(rowT + d.x) + atomicAdd(curT + d.x, 1)] = s.x;
    adjS[__ldg(rowS + s.x) + atomicAdd(curS + s.x, 1)] = d.x;
    adjT[__ldg(rowT + d.y) + atomicAdd(curT + d.y, 1)] = s.y;
    adjS[__ldg(rowS + s.y) + atomicAdd(curS + s.y, 1)] = d.y;
}

// ---------------- warp-per-node mean aggregation (unroll x8) ----------------
__global__ void agg256_kernel(const __half* __restrict__ feat,
                              const int* __restrict__ rowp,
                              const int* __restrict__ adj,
                              __half* __restrict__ out, int nNodes) {
    int gw = (blockIdx.x * blockDim.x + threadIdx.x) >> 5;
    int lane = threadIdx.x & 31;
    if (gw >= nNodes) return;
    int s = __ldg(rowp + gw), e = __ldg(rowp + gw + 1);
    float acc[8] = {0.f, 0.f, 0.f, 0.f, 0.f, 0.f, 0.f, 0.f};
    const size_t lo = (size_t)lane * 8;
    int i = s;
    for (; i + 8 <= e; i += 8) {
        int nn[8];
#pragma unroll
        for (int q = 0; q < 8; q++) nn[q] = __ldg(adj + i + q);
        uint4 u[8];
#pragma unroll
        for (int q = 0; q < 8; q++) u[q] = *(const uint4*)(feat + (size_t)nn[q] * 256 + lo);
#pragma unroll
        for (int q = 0; q < 8; q++) {
            const __half2* h = (const __half2*)&u[q];
#pragma unroll
            for (int j = 0; j < 4; j++) {
                float2 f = __half22float2(h[j]);
                acc[2 * j]     += f.x;
                acc[2 * j + 1] += f.y;
            }
        }
    }
    for (; i + 4 <= e; i += 4) {
        int nn[4];
#pragma unroll
        for (int q = 0; q < 4; q++) nn[q] = __ldg(adj + i + q);
        uint4 u[4];
#pragma unroll
        for (int q = 0; q < 4; q++) u[q] = *(const uint4*)(feat + (size_t)nn[q] * 256 + lo);
#pragma unroll
        for (int q = 0; q < 4; q++) {
            const __half2* h = (const __half2*)&u[q];
#pragma unroll
            for (int j = 0; j < 4; j++) {
                float2 f = __half22float2(h[j]);
                acc[2 * j]     += f.x;
                acc[2 * j + 1] += f.y;
            }
        }
    }
    for (; i < e; i++) {
        int n0 = __ldg(adj + i);
        uint4 u0 = *(const uint4*)(feat + (size_t)n0 * 256 + lo);
        const __half2* h0 = (const __half2*)&u0;
#pragma unroll
        for (int j = 0; j < 4; j++) {
            float2 f0 = __half22float2(h0[j]);
            acc[2 * j]     += f0.x;
            acc[2 * j + 1] += f0.y;
        }
    }
    float inv = 1.f / fmaxf((float)(e - s), 1.f);
    __half2 o[4];
#pragma unroll
    for (int j = 0; j < 4; j++)
        o[j] = __floats2half2_rn(acc[2 * j] * inv, acc[2 * j + 1] * inv);
    *(uint4*)(out + (size_t)gw * 256 + lo) = *(uint4*)o;
}

__global__ void agg128_kernel(const __half* __restrict__ feat,
                              const int* __restrict__ rowp,
                              const int* __restrict__ adj,
                              __half* __restrict__ out, int nNodes) {
    int gw = (blockIdx.x * blockDim.x + threadIdx.x) >> 5;
    int lane = threadIdx.x & 31;
    if (gw >= nNodes) return;
    int s = __ldg(rowp + gw), e = __ldg(rowp + gw + 1);
    float acc[4] = {0.f, 0.f, 0.f, 0.f};
    const size_t lo = (size_t)lane * 4;
    int i = s;
    for (; i + 8 <= e; i += 8) {
        int nn[8];
#pragma unroll
        for (int q = 0; q < 8; q++) nn[q] = __ldg(adj + i + q);
        uint2 u[8];
#pragma unroll
        for (int q = 0; q < 8; q++) u[q] = *(const uint2*)(feat + (size_t)nn[q] * 128 + lo);
#pragma unroll
        for (int q = 0; q < 8; q++) {
            const __half2* h = (const __half2*)&u[q];
#pragma unroll
            for (int j = 0; j < 2; j++) {
                float2 f = __half22float2(h[j]);
                acc[2 * j]     += f.x;
                acc[2 * j + 1] += f.y;
            }
        }
    }
    for (; i + 4 <= e; i += 4) {
        int nn[4];
#pragma unroll
        for (int q = 0; q < 4; q++) nn[q] = __ldg(adj + i + q);
        uint2 u[4];
#pragma unroll
        for (int q = 0; q < 4; q++) u[q] = *(const uint2*)(feat + (size_t)nn[q] * 128 + lo);
#pragma unroll
        for (int q = 0; q < 4; q++) {
            const __half2* h = (const __half2*)&u[q];
#pragma unroll
            for (int j = 0; j < 2; j++) {
                float2 f = __half22float2(h[j]);
                acc[2 * j]     += f.x;
                acc[2 * j + 1] += f.y;
            }
        }
    }
    for (; i < e; i++) {
        int n0 = __ldg(adj + i);
        uint2 u0 = *(const uint2*)(feat + (size_t)n0 * 128 + lo);
        const __half2* h0 = (const __half2*)&u0;
#pragma unroll
        for (int j = 0; j < 2; j++) {
            float2 f0 = __half22float2(h0[j]);
            acc[2 * j]     += f0.x;
            acc[2 * j + 1] += f0.y;
        }
    }
    float inv = 1.f / fmaxf((float)(e - s), 1.f);
    __half2 o[2];
#pragma unroll
    for (int j = 0; j < 2; j++)
        o[j] = __floats2half2_rn(acc[2 * j] * inv, acc[2 * j + 1] * inv);
    *(uint2*)(out + (size_t)gw * 128 + lo) = *(uint2*)o;
}

// ---------------- fp16 HMMA GEMM machinery ----------------
#define A_ROW_B 80
#define B_ROW_B 528
#define A_STAGE_B (128*A_ROW_B)
#define B_STAGE_B (32*B_ROW_B)
#define STAGE_B   (A_STAGE_B + B_STAGE_B)
#define GEMM1_SMEM (4*STAGE_B)
#define H2_ROW_B 528
#define H2_TILE_B (128*H2_ROW_B)
#define GEMM2_SMEM (4*STAGE_B + H2_TILE_B)

__device__ __forceinline__ void mma_f16(float* d, const uint32_t* a, const uint32_t* b) {
    asm volatile(
        "mma.sync.aligned.m16n8k16.row.col.f32.f16.f16.f32 "
        "{%0,%1,%2,%3}, {%4,%5,%6,%7}, {%8,%9}, {%0,%1,%2,%3};"
        : "+f"(d[0]), "+f"(d[1]), "+f"(d[2]), "+f"(d[3])
        : "r"(a[0]), "r"(a[1]), "r"(a[2]), "r"(a[3]), "r"(b[0]), "r"(b[1]));
}
__device__ __forceinline__ void ldm_x4(uint32_t* r, uint32_t addr) {
    asm volatile("ldmatrix.sync.aligned.m8n8.x4.shared.b16 {%0,%1,%2,%3}, [%4];"
        : "=r"(r[0]), "=r"(r[1]), "=r"(r[2]), "=r"(r[3]) : "r"(addr));
}
__device__ __forceinline__ void ldm_x4t(uint32_t* r, uint32_t addr) {
    asm volatile("ldmatrix.sync.aligned.m8n8.x4.trans.shared.b16 {%0,%1,%2,%3}, [%4];"
        : "=r"(r[0]), "=r"(r[1]), "=r"(r[2]), "=r"(r[3]) : "r"(addr));
}

__device__ __forceinline__ void issue_ab(uint32_t sbase, int c, int k0, int K1,
                                         const __half* A1, const __half* A2, int K2,
                                         const __half* WTk, int bm, int Nrows, int tid) {
    int slot = c & 3;
    uint32_t aoff = sbase + slot * STAGE_B;
    uint32_t boff = aoff + A_STAGE_B;
    bool inA1 = (k0 < K1);
#pragma unroll
    for (int i = 0; i < 2; i++) {
        int idx = tid + i * 256;
        int row = idx >> 2, seg8 = (idx & 3) * 8;
        int grow = bm + row;
        bool ok = grow < Nrows;
        int gr = ok ? grow : 0;
        const __half* src = inA1 ? A1 + (size_t)gr * K1 + k0 + seg8
                                 : A2 + (size_t)gr * K2 + (k0 - K1) + seg8;
        uint32_t dst = aoff + (uint32_t)(row * A_ROW_B + seg8 * 2);
        int sz = ok ? 16 : 0;
        asm volatile("cp.async.cg.shared.global [%0], [%1], 16, %2;"
                     :: "r"(dst), "l"(src), "r"(sz));
    }
#pragma unroll
    for (int i = 0; i < 4; i++) {
        int idx = tid + i * 256;
        int kr = idx >> 5, seg = idx & 31;
        const __half* src = WTk + (size_t)(k0 + kr) * WROW + seg * 8;
        uint32_t dst = boff + (uint32_t)(kr * B_ROW_B + seg * 16);
        asm volatile("cp.async.cg.shared.global [%0], [%1], 16;"
                     :: "r"(dst), "l"(src));
    }
    asm volatile("cp.async.commit_group;");
}

__device__ __forceinline__ void issue_b(uint32_t sbase, int c, const __half* P, int tid) {
    int slot = c & 3;
    uint32_t boff = sbase + slot * STAGE_B + A_STAGE_B;
    int k0 = c << 5;
#pragma unroll
    for (int i = 0; i < 4; i++) {
        int idx = tid + i * 256;
        int kr = idx >> 5, seg = idx & 31;
        const __half* src = P + (size_t)(k0 + kr) * WROW + seg * 8;
        uint32_t dst = boff + (uint32_t)(kr * B_ROW_B + seg * 16);
        asm volatile("cp.async.cg.shared.global [%0], [%1], 16;"
                     :: "r"(dst), "l"(src));
    }
    asm volatile("cp.async.commit_group;");
}

__device__ __forceinline__ void mma_chunk(uint32_t aBase, uint32_t bBase, float acc[4][8][4]) {
#pragma unroll
    for (int s = 0; s < 2; s++) {
        uint32_t af[4][4], bf[4][4];
#pragma unroll
        for (int mt = 0; mt < 4; mt++)
            ldm_x4(af[mt], aBase + mt * (16 * A_ROW_B) + s * 32);
#pragma unroll
        for (int p = 0; p < 4; p++)
            ldm_x4t(bf[p], bBase + s * (16 * B_ROW_B) + p * 32);
#pragma unroll
        for (int mt = 0; mt < 4; mt++)
#pragma unroll
            for (int p = 0; p < 4; p++) {
                mma_f16(acc[mt][2 * p],     af[mt], &bf[p][0]);
                mma_f16(acc[mt][2 * p + 1], af[mt], &bf[p][2]);
            }
    }
}

// ---------------- layer-1 / plain GEMM: optional relu epilogue ----------------
__global__ void __launch_bounds__(256)
gemm_sage(const __half* A1, int K1, const __half* A2, int K2,
          const __half* W, const float* bias, __half* C, int Nrows, int doRelu) {
    extern __shared__ char sm[];
    const int tid = threadIdx.x;
    const int wid = tid >> 5, lane = tid & 31;
    const int warpM = wid >> 2, warpN = wid & 3;
    const int lrow = lane >> 2, lcol = lane & 3;
    const int bm = blockIdx.x * 128;
    const int nch = (K1 + K2) >> 5;

    uint32_t sbase = (uint32_t)__cvta_generic_to_shared(sm);
    const uint32_t aLane = (uint32_t)((warpM * 64 + (lane & 15)) * A_ROW_B + ((lane & 16) ? 16 : 0));
    const uint32_t bLane = (uint32_t)((lane & 15) * B_ROW_B + (warpN * 64 + ((lane & 16) ? 8 : 0)) * 2);

    float2 bv[8];
#pragma unroll
    for (int nt = 0; nt < 8; nt++) {
        int col = warpN * 64 + nt * 8 + 2 * lcol;
        bv[nt].x = __ldg(bias + col); bv[nt].y = __ldg(bias + col + 1);
    }

    float acc[4][8][4];
#pragma unroll
    for (int i = 0; i < 4; i++)
#pragma unroll
        for (int j = 0; j < 8; j++)
#pragma unroll
            for (int q = 0; q < 4; q++) acc[i][j][q] = 0.f;

    issue_ab(sbase, 0, 0, K1, A1, A2, K2, W, bm, Nrows, tid);
    issue_ab(sbase, 1, 32, K1, A1, A2, K2, W, bm, Nrows, tid);
    issue_ab(sbase, 2, 64, K1, A1, A2, K2, W, bm, Nrows, tid);

    for (int c = 0; c < nch; c++) {
        asm volatile("cp.async.wait_group 2;");
        __syncthreads();
        if (c + 3 < nch) issue_ab(sbase, c + 3, (c + 3) << 5, K1, A1, A2, K2, W, bm, Nrows, tid);
        else asm volatile("cp.async.commit_group;");
        int slot = c & 3;
        mma_chunk(sbase + slot * STAGE_B + aLane,
                  sbase + slot * STAGE_B + A_STAGE_B + bLane, acc);
    }

#pragma unroll
    for (int mt = 0; mt < 4; mt++) {
        const int r0 = bm + warpM * 64 + mt * 16 + lrow;
#pragma unroll
        for (int half = 0; half < 2; half++) {
            const int row = r0 + half * 8;
            if (row >= Nrows) continue;
#pragma unroll
            for (int nt = 0; nt < 8; nt++) {
                const int col = warpN * 64 + nt * 8 + 2 * lcol;
                float vx = acc[mt][nt][half * 2 + 0] + bv[nt].x;
                float vy = acc[mt][nt][half * 2 + 1] + bv[nt].y;
                if (doRelu) { vx = fmaxf(vx, 0.f); vy = fmaxf(vy, 0.f); }
                *(__half2*)(C + (size_t)row * 256 + col) = __floats2half2_rn(vx, vy);
            }
        }
    }
}

// ---------------- taxon layer-2 GEMM + fused projection (K=512) ----------------
__global__ void __launch_bounds__(256)
gemm_l2p(const __half* A1, const __half* A2, const __half* W, const float* bias,
         const __half* P, __half* U, int Nrows) {
    extern __shared__ char sm[];
    const int tid = threadIdx.x;
    const int wid = tid >> 5, lane = tid & 31;
    const int warpM = wid >> 2, warpN = wid & 3;
    const int lrow = lane >> 2, lcol = lane & 3;
    const int bm = blockIdx.x * 128;
    const int K1 = HID;
    const int nch = 16;

    uint32_t sbase = (uint32_t)__cvta_generic_to_shared(sm);
    uint32_t* H2 = (uint32_t*)(sm + 4 * STAGE_B);
    const uint32_t h2base = sbase + 4 * STAGE_B;
    const uint32_t aLane = (uint32_t)((warpM * 64 + (lane & 15)) * A_ROW_B + ((lane & 16) ? 16 : 0));
    const uint32_t bLane = (uint32_t)((lane & 15) * B_ROW_B + (warpN * 64 + ((lane & 16) ? 8 : 0)) * 2);
    const uint32_t h2Lane = h2base + (uint32_t)((warpM * 64 + (lane & 15)) * H2_ROW_B + ((lane & 16) ? 16 : 0));

    float2 bv[8];
#pragma unroll
    for (int nt = 0; nt < 8; nt++) {
        int col = warpN * 64 + nt * 8 + 2 * lcol;
        bv[nt].x = __ldg(bias + col); bv[nt].y = __ldg(bias + col + 1);
    }

    float acc[4][8][4];
#pragma unroll
    for (int i = 0; i < 4; i++)
#pragma unroll
        for (int j = 0; j < 8; j++)
#pragma unroll
            for (int q = 0; q < 4; q++) acc[i][j][q] = 0.f;

    issue_ab(sbase, 0, 0, K1, A1, A2, HID, W, bm, Nrows, tid);
    issue_ab(sbase, 1, 32, K1, A1, A2, HID, W, bm, Nrows, tid);
    issue_ab(sbase, 2, 64, K1, A1, A2, HID, W, bm, Nrows, tid);

    for (int c = 0; c < nch; c++) {
        asm volatile("cp.async.wait_group 2;");
        __syncthreads();
        if (c + 3 < nch) issue_ab(sbase, c + 3, (c + 3) << 5, K1, A1, A2, HID, W, bm, Nrows, tid);
        else asm volatile("cp.async.commit_group;");
        int slot = c & 3;
        mma_chunk(sbase + slot * STAGE_B + aLane,
                  sbase + slot * STAGE_B + A_STAGE_B + bLane, acc);
    }

#pragma unroll
    for (int mt = 0; mt < 4; mt++) {
#pragma unroll
        for (int half = 0; half < 2; half++) {
            const int row = warpM * 64 + mt * 16 + lrow + half * 8;
#pragma unroll
            for (int nt = 0; nt < 8; nt++) {
                const int col2 = warpN * 32 + nt * 4 + lcol;
                float vx = fmaxf(acc[mt][nt][half * 2 + 0] + bv[nt].x, 0.f);
                float vy = fmaxf(acc[mt][nt][half * 2 + 1] + bv[nt].y, 0.f);
                __half2 hv = __floats2half2_rn(vx, vy);
                H2[row * (H2_ROW_B / 4) + col2] = *(uint32_t*)&hv;
            }
        }
    }
#pragma unroll
    for (int i = 0; i < 4; i++)
#pragma unroll
        for (int j = 0; j < 8; j++)
#pragma unroll
            for (int q = 0; q < 4; q++) acc[i][j][q] = 0.f;
    __syncthreads();

    issue_b(sbase, 0, P, tid);
    issue_b(sbase, 1, P, tid);
    issue_b(sbase, 2, P, tid);

    for (int c = 0; c < 8; c++) {
        asm volatile("cp.async.wait_group 2;");
        __syncthreads();
        if (c + 3 < 8) issue_b(sbase, c + 3, P, tid);
        else asm volatile("cp.async.commit_group;");
        int slot = c & 3;
        uint32_t bB = sbase + slot * STAGE_B + A_STAGE_B + bLane;
#pragma unroll
        for (int s = 0; s < 2; s++) {
            uint32_t af[4][4], bf[4][4];
#pragma unroll
            for (int mt = 0; mt < 4; mt++)
                ldm_x4(af[mt], h2Lane + mt * (16 * H2_ROW_B) + c * 64 + s * 32);
#pragma unroll
            for (int p = 0; p < 4; p++)
                ldm_x4t(bf[p], bB + s * (16 * B_ROW_B) + p * 32);
#pragma unroll
            for (int mt = 0; mt < 4; mt++)
#pragma unroll
                for (int p = 0; p < 4; p++) {
                    mma_f16(acc[mt][2 * p],     af[mt], &bf[p][0]);
                    mma_f16(acc[mt][2 * p + 1], af[mt], &bf[p][2]);
                }
        }
    }

#pragma unroll
    for (int mt = 0; mt < 4; mt++) {
        const int r0 = bm + warpM * 64 + mt * 16 + lrow;
#pragma unroll
        for (int half = 0; half < 2; half++) {
            const int row = r0 + half * 8;
            if (row >= Nrows) continue;
#pragma unroll
            for (int nt = 0; nt < 8; nt++) {
                const int col = warpN * 64 + nt * 8 + 2 * lcol;
                *(__half2*)(U + (size_t)row * 256 + col) =
                    __floats2half2_rn(acc[mt][nt][half * 2 + 0], acc[mt][nt][half * 2 + 1]);
            }
        }
    }
}

// ---------------- sotu layer-2 GEMM (K=256) + aggP add + fused projection ----------------
// h2 = relu(A1 @ Wr2^T + AGGP + bias); u = h2 @ P. AGGP tile prefetched into H2 smem.
__global__ void __launch_bounds__(256)
gemm_l2s(const __half* A1, const __half* W, const float* bias,
         const __half* AGGP, const __half* P, __half* U, int Nrows) {
    extern __shared__ char sm[];
    const int tid = threadIdx.x;
    const int wid = tid >> 5, lane = tid & 31;
    const int warpM = wid >> 2, warpN = wid & 3;
    const int lrow = lane >> 2, lcol = lane & 3;
    const int bm = blockIdx.x * 128;
    const int nch = 8;   // K = 256

    uint32_t sbase = (uint32_t)__cvta_generic_to_shared(sm);
    uint32_t* H2 = (uint32_t*)(sm + 4 * STAGE_B);
    const uint32_t h2base = sbase + 4 * STAGE_B;
    const uint32_t aLane = (uint32_t)((warpM * 64 + (lane & 15)) * A_ROW_B + ((lane & 16) ? 16 : 0));
    const uint32_t bLane = (uint32_t)((lane & 15) * B_ROW_B + (warpN * 64 + ((lane & 16) ? 8 : 0)) * 2);
    const uint32_t h2Lane = h2base + (uint32_t)((warpM * 64 + (lane & 15)) * H2_ROW_B + ((lane & 16) ? 16 : 0));

    // prefetch aggP tile (128 rows x 512B) into H2 region (oldest cp.async group)
#pragma unroll
    for (int i = 0; i < 16; i++) {
        int idx = tid + i * 256;
        int row = idx >> 5, seg = idx & 31;
        int grow = bm + row;
        bool ok = grow < Nrows;
        const __half* src = AGGP + (size_t)(ok ? grow : 0) * 256 + seg * 8;
        uint32_t dst = h2base + (uint32_t)(row * H2_ROW_B + seg * 16);
        int sz = ok ? 16 : 0;
        asm volatile("cp.async.cg.shared.global [%0], [%1], 16, %2;"
                     :: "r"(dst), "l"(src), "r"(sz));
    }
    asm volatile("cp.async.commit_group;");

    float2 bv[8];
#pragma unroll
    for (int nt = 0; nt < 8; nt++) {
        int col = warpN * 64 + nt * 8 + 2 * lcol;
        bv[nt].x = __ldg(bias + col); bv[nt].y = __ldg(bias + col + 1);
    }

    float acc[4][8][4];
#pragma unroll
    for (int i = 0; i < 4; i++)
#pragma unroll
        for (int j = 0; j < 8; j++)
#pragma unroll
            for (int q = 0; q < 4; q++) acc[i][j][q] = 0.f;

    issue_ab(sbase, 0, 0, HID, A1, (const __half*)0, HID, W, bm, Nrows, tid);
    issue_ab(sbase, 1, 32, HID, A1, (const __half*)0, HID, W, bm, Nrows, tid);
    issue_ab(sbase, 2, 64, HID, A1, (const __half*)0, HID, W, bm, Nrows, tid);

    for (int c = 0; c < nch; c++) {
        asm volatile("cp.async.wait_group 2;");
        __syncthreads();
        if (c + 3 < nch) issue_ab(sbase, c + 3, (c + 3) << 5, HID, A1, (const __half*)0, HID, W, bm, Nrows, tid);
        else asm volatile("cp.async.commit_group;");
        int slot = c & 3;
        mma_chunk(sbase + slot * STAGE_B + aLane,
                  sbase + slot * STAGE_B + A_STAGE_B + bLane, acc);
    }
    // ensure aggP tile (and trailing empty groups) are fully landed before reading H2
    asm volatile("cp.async.wait_group 0;");
    __syncthreads();

    // h2 = relu(acc + bias + aggP); write h2 into H2 (same slots)
#pragma unroll
    for (int mt = 0; mt < 4; mt++) {
#pragma unroll
        for (int half = 0; half < 2; half++) {
            const int row = warpM * 64 + mt * 16 + lrow + half * 8;
#pragma unroll
            for (int nt = 0; nt < 8; nt++) {
                const int col2 = warpN * 32 + nt * 4 + lcol;
                uint32_t praw = H2[row * (H2_ROW_B / 4) + col2];
                float2 pf = __half22float2(*(__half2*)&praw);
                float vx = fmaxf(acc[mt][nt][half * 2 + 0] + bv[nt].x + pf.x, 0.f);
                float vy = fmaxf(acc[mt][nt][half * 2 + 1] + bv[nt].y + pf.y, 0.f);
                __half2 hv = __floats2half2_rn(vx, vy);
                H2[row * (H2_ROW_B / 4) + col2] = *(uint32_t*)&hv;
            }
        }
    }
#pragma unroll
    for (int i = 0; i < 4; i++)
#pragma unroll
        for (int j = 0; j < 8; j++)
#pragma unroll
            for (int q = 0; q < 4; q++) acc[i][j][q] = 0.f;
    __syncthreads();

    // projection loop: u = h2 @ P
    issue_b(sbase, 0, P, tid);
    issue_b(sbase, 1, P, tid);
    issue_b(sbase, 2, P, tid);

    for (int c = 0; c < 8; c++) {
        asm volatile("cp.async.wait_group 2;");
        __syncthreads();
        if (c + 3 < 8) issue_b(sbase, c + 3, P, tid);
        else asm volatile("cp.async.commit_group;");
        int slot = c & 3;
        uint32_t bB = sbase + slot * STAGE_B + A_STAGE_B + bLane;
#pragma unroll
        for (int s = 0; s < 2; s++) {
            uint32_t af[4][4], bf[4][4];
#pragma unroll
            for (int mt = 0; mt < 4; mt++)
                ldm_x4(af[mt], h2Lane + mt * (16 * H2_ROW_B) + c * 64 + s * 32);
#pragma unroll
            for (int p = 0; p < 4; p++)
                ldm_x4t(bf[p], bB + s * (16 * B_ROW_B) + p * 32);
#pragma unroll
            for (int mt = 0; mt < 4; mt++)
#pragma unroll
                for (int p = 0; p < 4; p++) {
                    mma_f16(acc[mt][2 * p],     af[mt], &bf[p][0]);
                    mma_f16(acc[mt][2 * p + 1], af[mt], &bf[p][2]);
                }
        }
    }

#pragma unroll
    for (int mt = 0; mt < 4; mt++) {
        const int r0 = bm + warpM * 64 + mt * 16 + lrow;
#pragma unroll
        for (int half = 0; half < 2; half++) {
            const int row = r0 + half * 8;
            if (row >= Nrows) continue;
#pragma unroll
            for (int nt = 0; nt < 8; nt++) {
                const int col = warpN * 64 + nt * 8 + 2 * lcol;
                *(__half2*)(U + (size_t)row * 256 + col) =
                    __floats2half2_rn(acc[mt][nt][half * 2 + 0], acc[mt][nt][half * 2 + 1]);
            }
        }
    }
}

// ---------------- weight composition (k-major half output) ----------------
__global__ void compose_kernel(const float* __restrict__ Wd1,
                               const float* __restrict__ Wlin_s,
                               const float* __restrict__ Wlin_t,
                               const float* __restrict__ blin_s,
                               const float* __restrict__ blin_t,
                               const float* __restrict__ bd1,
                               __half* WcsT, __half* WctT, float* bdc) {
    int i = blockIdx.x;
    int m = threadIdx.x;
    float ss = 0.f, st = 0.f;
    for (int k = 0; k < HID; k++) {
        float wl = Wd1[i * 2 * HID + k];
        float wr = Wd1[i * 2 * HID + HID + k];
        ss += wl * Wlin_s[k * HID + m];
        st += wr * Wlin_t[k * HID + m];
    }
    WcsT[(size_t)m * WROW + i] = __float2half_rn(ss);
    WctT[(size_t)m * WROW + i] = __float2half_rn(st);
    if (m == 0) {
        float b = bd1[i];
        for (int k = 0; k < HID; k++) {
            b += Wd1[i * 2 * HID + k] * blin_s[k];
            b += Wd1[i * 2 * HID + HID + k] * blin_t[k];
        }
        bdc[i] = b;
    }
}

// ---------------- decoder: 2 edges per warp ----------------
__global__ void decode_kernel(const __half* __restrict__ us, const __half* __restrict__ ut,
                              const int* __restrict__ ls, const int* __restrict__ ld,
                              const float* __restrict__ bdc, const float* __restrict__ wd2,
                              const float* __restrict__ bd2,
                              float* __restrict__ out, int EL2) {
    int g = blockIdx.x * blockDim.x + threadIdx.x;
    int w = g >> 5, lane = g & 31;
    if (w >= EL2) return;
    int half = lane >> 4, l16 = lane & 15;
    int edge = w * 2 + half;
    const uint4* a = (const uint4*)(us + (size_t)__ldg(ls + edge) * HID) + l16 * 2;
    const uint4* b = (const uint4*)(ut + (size_t)__ldg(ld + edge) * HID) + l16 * 2;
    uint4 ua0 = a[0], ua1 = a[1];
    uint4 ub0 = b[0], ub1 = b[1];
    float cb[16], wb[16];
#pragma unroll
    for (int j = 0; j < 4; j++) {
        *(float4*)&cb[j * 4] = __ldg((const float4*)bdc + l16 * 4 + j);
        *(float4*)&wb[j * 4] = __ldg((const float4*)wd2 + l16 * 4 + j);
    }
    const __half2* ha0 = (const __half2*)&ua0;
    const __half2* ha1 = (const __half2*)&ua1;
    const __half2* hb0 = (const __half2*)&ub0;
    const __half2* hb1 = (const __half2*)&ub1;
    float sum = 0.f;
#pragma unroll
    for (int k = 0; k < 4; k++) {
        float2 fa = __half22float2(ha0[k]), fb = __half22float2(hb0[k]);
        sum += fmaxf(fa.x + fb.x + cb[2 * k], 0.f) * wb[2 * k]
             + fmaxf(fa.y + fb.y + cb[2 * k + 1], 0.f) * wb[2 * k + 1];
    }
#pragma unroll
    for (int k = 0; k < 4; k++) {
        float2 fa = __half22float2(ha1[k]), fb = __half22float2(hb1[k]);
        sum += fmaxf(fa.x + fb.x + cb[8 + 2 * k], 0.f) * wb[8 + 2 * k]
             + fmaxf(fa.y + fb.y + cb[8 + 2 * k + 1], 0.f) * wb[8 + 2 * k + 1];
    }
#pragma unroll
    for (int o = 8; o; o >>= 1) sum += __shfl_xor_sync(0xffffffffu, sum, o);
    if (l16 == 0) out[edge] = sum + bd2[0];
}

// ---------------- launcher (R9 schedule + commuted sotu L2) ----------------
extern "C" void kernel_launch(void* const* d_in, const int* in_sizes, int n_in,
                              void* d_out, int out_size) {
    const float* x_sotu  = (const float*)d_in[0];
    const float* x_taxon = (const float*)d_in[1];
    const int*   esrc    = (const int*)d_in[2];
    const int*   edst    = (const int*)d_in[3];
    const int*   lsrc    = (const int*)d_in[4];
    const int*   ldst    = (const int*)d_in[5];
    const float* Wl1_st  = (const float*)d_in[6];
    const float* bl1_st  = (const float*)d_in[7];
    const float* Wr1_st  = (const float*)d_in[8];
    const float* Wl1_ts  = (const float*)d_in[9];
    const float* bl1_ts  = (const float*)d_in[10];
    const float* Wr1_ts  = (const float*)d_in[11];
    const float* Wl2_st  = (const float*)d_in[12];
    const float* bl2_st  = (const float*)d_in[13];
    const float* Wr2_st  = (const float*)d_in[14];
    const float* Wl2_ts  = (const float*)d_in[15];
    const float* bl2_ts  = (const float*)d_in[16];
    const float* Wr2_ts  = (const float*)d_in[17];
    const float* Wlin_s  = (const float*)d_in[18];
    const float* blin_s  = (const float*)d_in[19];
    const float* Wlin_t  = (const float*)d_in[20];
    const float* blin_t  = (const float*)d_in[21];
    const float* Wd1     = (const float*)d_in[22];
    const float* bd1     = (const float*)d_in[23];
    const float* Wd2     = (const float*)d_in[24];
    const float* bd2     = (const float*)d_in[25];
    float* out = (float*)d_out;

    float *bdc, *zerob;
    __half *aggTh, *aggSh, *h1t, *h1s, *p1t, *us, *ut;
    __half *xrs, *xrt, *wt1st, *wt1ts, *wt2st, *wt2ts, *wcsT, *wctT;
    int *rowT, *rowS, *curT, *curS, *adjT, *adjS, *bsums;
    cudaGetSymbolAddress((void**)&aggTh, g_aggTh);
    cudaGetSymbolAddress((void**)&aggSh, g_aggSh);
    cudaGetSymbolAddress((void**)&h1t, g_h1t);
    cudaGetSymbolAddress((void**)&h1s, g_h1s);
    cudaGetSymbolAddress((void**)&p1t, g_p1t);
    cudaGetSymbolAddress((void**)&us,  g_us);
    cudaGetSymbolAddress((void**)&ut,  g_ut);
    cudaGetSymbolAddress((void**)&xrs, g_xr_s);
    cudaGetSymbolAddress((void**)&xrt, g_xr_t);
    cudaGetSymbolAddress((void**)&wt1st, g_wt1_st);
    cudaGetSymbolAddress((void**)&wt1ts, g_wt1_ts);
    cudaGetSymbolAddress((void**)&wt2st, g_wt2_st);
    cudaGetSymbolAddress((void**)&wt2ts, g_wt2_ts);
    cudaGetSymbolAddress((void**)&wcsT, g_wcsT);
    cudaGetSymbolAddress((void**)&wctT, g_wctT);
    cudaGetSymbolAddress((void**)&bdc, g_bdc);
    cudaGetSymbolAddress((void**)&zerob, g_zero);
    cudaGetSymbolAddress((void**)&rowT, g_rowT);
    cudaGetSymbolAddress((void**)&rowS, g_rowS);
    cudaGetSymbolAddress((void**)&curT, g_curT);
    cudaGetSymbolAddress((void**)&curS, g_curS);
    cudaGetSymbolAddress((void**)&adjT, g_adjT);
    cudaGetSymbolAddress((void**)&adjS, g_adjS);
    cudaGetSymbolAddress((void**)&bsums, g_bsums);

    static cudaStream_t s2 = nullptr;
    static cudaEvent_t ev[8];
    static int inited = 0;
    if (!inited) {
        cudaFuncSetAttribute(gemm_sage, cudaFuncAttributeMaxDynamicSharedMemorySize, GEMM1_SMEM);
        cudaFuncSetAttribute(gemm_l2p, cudaFuncAttributeMaxDynamicSharedMemorySize, GEMM2_SMEM);
        cudaFuncSetAttribute(gemm_l2s, cudaFuncAttributeMaxDynamicSharedMemorySize, GEMM2_SMEM);
        cudaStreamCreateWithFlags(&s2, cudaStreamNonBlocking);
        for (int i = 0; i < 8; i++) cudaEventCreateWithFlags(&ev[i], cudaEventDisableTiming);
        inited = 1;
    }
    cudaStream_t s0 = 0;

    const int gT = (N_TAXON + 127) / 128;   // 157
    const int gS = (N_SOTU + 127) / 128;    // 782
    const unsigned wT = (N_TAXON * 32 + 255) / 256;
    const unsigned wS = (N_SOTU * 32 + 255) / 256;

    // ---- fork 1: prep on s0 || CSR on s2 ----
    cudaEventRecord(ev[0], s0);
    cudaStreamWaitEvent(s2, ev[0], 0);

    long long nxs4 = (long long)N_SOTU * DS / 4, nxt4 = (long long)N_TAXON * DT / 4;
    tohalf_dual<<<(unsigned)((nxs4 + nxt4 + 255) / 256), 256, 0, s0>>>(
        (const float4*)x_sotu, (__half2*)xrs, nxs4,
        (const float4*)x_taxon, (__half2*)xrt, nxt4);
    wt_all<<<1792, 256, 0, s0>>>(Wl1_st, Wr1_st, wt1st,
                                 Wl1_ts, Wr1_ts, wt1ts,
                                 Wl2_st, Wr2_st, wt2st,
                                 Wl2_ts, Wr2_ts, wt2ts);
    compose_kernel<<<HID, HID, 0, s0>>>(Wd1, Wlin_s, Wlin_t, blin_s, blin_t, bd1, wcsT, wctT, bdc);

    zero_dual<<<(N_SOTU + 255) / 256, 256, 0, s2>>>(curT, N_TAXON, curS, N_SOTU);
    hist_kernel<<<(NE / 2 + 255) / 256, 256, 0, s2>>>(
        (const int2*)esrc, (const int2*)edst, curS, curT, NE / 2);
    scan_local<<<NBT, 1024, 0, s2>>>(curT, rowT, N_TAXON, curS, rowS, N_SOTU, bsums);
    scan_partials<<<1, 128, 0, s2>>>(bsums, rowT, N_TAXON, rowS, N_SOTU);
    scan_add<<<NBT, 1024, 0, s2>>>(rowT, N_TAXON, rowS, N_SOTU, bsums);
    fill_kernel<<<(NE / 2 + 255) / 256, 256, 0, s2>>>(
        (const int2*)esrc, (const int2*)edst, rowT, curT, adjT, rowS, curS, adjS, NE / 2);

    // ---- join, then fork 2: layer-1 taxon chain (+p1t) on s0 || sotu chain on s2 ----
    cudaEventRecord(ev[1], s2);
    cudaStreamWaitEvent(s0, ev[1], 0);
    cudaEventRecord(ev[2], s0);
    cudaStreamWaitEvent(s2, ev[2], 0);

    agg256_kernel<<<wT, 256, 0, s0>>>(xrs, rowT, adjT, aggTh, N_TAXON);
    gemm_sage<<<(unsigned)gT, 256, GEMM1_SMEM, s0>>>(aggTh, DS, xrt, DT, wt1st, bl1_st, h1t, N_TAXON, 1);
    // p1t = h1t @ Wl2_ts^T  (20K rows, K=256; wt2ts rows [0,256) hold Wl2_ts k-major)
    gemm_sage<<<(unsigned)gT, 256, GEMM1_SMEM, s0>>>(h1t, HID, (const __half*)0, 0,
                                                     wt2ts, zerob, p1t, N_TAXON, 0);

    agg128_kernel<<<wS, 256, 0, s2>>>(xrt, rowS, adjS, aggSh, N_SOTU);
    gemm_sage<<<(unsigned)gS, 256, GEMM1_SMEM, s2>>>(aggSh, DT, xrs, DS, wt1ts, bl1_ts, h1s, N_SOTU, 1);

    // ---- join (layer 2 needs both sides), fork 3 ----
    cudaEventRecord(ev[3], s2);
    cudaStreamWaitEvent(s0, ev[3], 0);
    cudaEventRecord(ev[4], s0);
    cudaStreamWaitEvent(s2, ev[4], 0);

    agg256_kernel<<<wT, 256, 0, s0>>>(h1s, rowT, adjT, aggTh, N_TAXON);
    gemm_l2p<<<(unsigned)gT, 256, GEMM2_SMEM, s0>>>(aggTh, h1t, wt2st, bl2_st, wctT, ut, N_TAXON);

    agg256_kernel<<<wS, 256, 0, s2>>>(p1t, rowS, adjS, aggSh, N_SOTU);
    gemm_l2s<<<(unsigned)gS, 256, GEMM2_SMEM, s2>>>(h1s, wt2ts + (size_t)256 * WROW, bl2_ts,
                                                    aggSh, wcsT, us, N_SOTU);

    // ---- join, decode on s0 ----
    cudaEventRecord(ev[5], s2);
    cudaStreamWaitEvent(s0, ev[5], 0);

    decode_kernel<<<(NEL / 2 * 32 + 255) / 256, 256, 0, s0>>>(
        us, ut, lsrc, ldst, bdc, Wd2, bd2, out, NEL / 2);
}